// round 13
// baseline (speedup 1.0000x reference)
#include <cuda_runtime.h>
#include <cuda_bf16.h>
#include <cuda_fp16.h>
#include <math.h>
#include <stdint.h>

#define NB 8
#define NL 1024
#define ND 512
#define NH 8
#define NDH 64
#define TOK (NB * NL)
#define ACT_ELEMS ((size_t)TOK * ND)
#define W_ELEMS ((size_t)ND * ND)
#define ATT_ELEMS ((size_t)NB * NH * NL * NL)
#define MASK_WORDS (ATT_ELEMS / 32)

// per-path staging buffers (no false deps between Q/K/V pipelines)
__device__ __nv_bfloat16 g_QAh[ACT_ELEMS], g_QAl[ACT_ELEMS];
__device__ __nv_bfloat16 g_KAh[ACT_ELEMS], g_KAl[ACT_ELEMS];
__device__ __nv_bfloat16 g_VAh[ACT_ELEMS], g_VAl[ACT_ELEMS];
__device__ __nv_bfloat16 g_WQh[W_ELEMS], g_WQl[W_ELEMS];
__device__ __nv_bfloat16 g_WKh[W_ELEMS], g_WKl[W_ELEMS];
__device__ __nv_bfloat16 g_WVh[W_ELEMS], g_WVl[W_ELEMS];
__device__ __nv_bfloat16 g_WOh[W_ELEMS], g_WOl[W_ELEMS];
__device__ __half       g_Qf[ACT_ELEMS], g_Kf[ACT_ELEMS];     // single f16
__device__ __half       g_Vth[ACT_ELEMS], g_Vtl[ACT_ELEMS];   // [bh*64+d][1024] f16 hi/lo
__device__ __nv_bfloat16 g_Ch[ACT_ELEMS], g_Cl[ACT_ELEMS];
__device__ float        g_projf[ACT_ELEMS];
__device__ unsigned     g_am[MASK_WORDS], g_sm[MASK_WORDS];
__device__ int          g_mask_mode;

// ---------------- helpers ----------------
__device__ __forceinline__ uint32_t smem_u32(const void* p) {
    uint32_t a;
    asm("{ .reg .u64 t; cvta.to.shared.u64 t, %1; cvt.u32.u64 %0, t; }" : "=r"(a) : "l"(p));
    return a;
}
__device__ __forceinline__ void ldm_x4(unsigned r[4], uint32_t a) {
    asm volatile("ldmatrix.sync.aligned.m8n8.x4.shared.b16 {%0,%1,%2,%3}, [%4];"
                 : "=r"(r[0]), "=r"(r[1]), "=r"(r[2]), "=r"(r[3]) : "r"(a) : "memory");
}
#define MMA(c, a, b) \
    asm volatile("mma.sync.aligned.m16n8k16.row.col.f32.bf16.bf16.f32 " \
                 "{%0,%1,%2,%3},{%4,%5,%6,%7},{%8,%9},{%0,%1,%2,%3};" \
                 : "+f"((c)[0]), "+f"((c)[1]), "+f"((c)[2]), "+f"((c)[3]) \
                 : "r"((a)[0]), "r"((a)[1]), "r"((a)[2]), "r"((a)[3]), \
                   "r"((b)[0]), "r"((b)[1]))
#define MMAH(c, a, b) \
    asm volatile("mma.sync.aligned.m16n8k16.row.col.f32.f16.f16.f32 " \
                 "{%0,%1,%2,%3},{%4,%5,%6,%7},{%8,%9},{%0,%1,%2,%3};" \
                 : "+f"((c)[0]), "+f"((c)[1]), "+f"((c)[2]), "+f"((c)[3]) \
                 : "r"((a)[0]), "r"((a)[1]), "r"((a)[2]), "r"((a)[3]), \
                   "r"((b)[0]), "r"((b)[1]))

#define CP16(dst, src) \
    asm volatile("cp.async.cg.shared.global [%0], [%1], 16;" :: "r"(dst), "l"(src) : "memory")
#define CP_COMMIT() asm volatile("cp.async.commit_group;" ::: "memory")
#define CP_WAIT(n)  asm volatile("cp.async.wait_group %0;" :: "n"(n) : "memory")

__device__ __forceinline__ void split2(float f0, float f1, unsigned& hp, unsigned& lp) {
    __nv_bfloat16 h0 = __float2bfloat16_rn(f0), h1 = __float2bfloat16_rn(f1);
    __nv_bfloat16 l0 = __float2bfloat16_rn(f0 - __bfloat162float(h0));
    __nv_bfloat16 l1 = __float2bfloat16_rn(f1 - __bfloat162float(h1));
    hp = (unsigned)__bfloat16_as_ushort(h0) | ((unsigned)__bfloat16_as_ushort(h1) << 16);
    lp = (unsigned)__bfloat16_as_ushort(l0) | ((unsigned)__bfloat16_as_ushort(l1) << 16);
}
__device__ __forceinline__ unsigned packh2(float f0, float f1) {
    __half2 h = __floats2half2_rn(f0, f1);
    return *(unsigned*)&h;
}

// degree-4 exp2 on fma pipe; rel err ~3e-6
__device__ __forceinline__ float fexp2(float x) {
    x = fmaxf(fminf(x, 120.0f), -126.0f);
    float fl = floorf(x);
    float f = x - fl;
    float p = 1.35557472e-2f;
    p = fmaf(p, f, 5.20323690e-2f);
    p = fmaf(p, f, 2.41379774e-1f);
    p = fmaf(p, f, 6.93018210e-1f);
    p = fmaf(p, f, 1.00000370f);
    return __int_as_float(__float_as_int(p) + (((int)fl) << 23));
}

// ---------------- prep kernels ----------------
__global__ void detect_mask_kernel(const unsigned* __restrict__ m) {
    __shared__ int f32flag, u8flag;
    if (threadIdx.x == 0) { f32flag = 0; u8flag = 0; }
    __syncthreads();
    int lf = 0, lu = 0;
    for (int i = threadIdx.x; i < 4096; i += blockDim.x) {
        unsigned w = m[i];
        if (w == 0x3f800000u) lf = 1;
        else if (w > 1u) lu = 1;
    }
    if (lf) atomicOr(&f32flag, 1);
    if (lu) atomicOr(&u8flag, 1);
    __syncthreads();
    if (threadIdx.x == 0) g_mask_mode = f32flag ? 2 : (u8flag ? 0 : 1);
}

__global__ void pack_mask_kernel(const void* __restrict__ m, unsigned* __restrict__ out) {
    int w = blockIdx.x * 256 + threadIdx.x;
    if (w >= (int)MASK_WORDS) return;
    int mode = g_mask_mode;
    unsigned bits = 0;
    if (mode == 0) {
        const unsigned* p = (const unsigned*)m + (size_t)w * 8;
#pragma unroll
        for (int j = 0; j < 8; j++) {
            unsigned v = __vcmpne4(p[j], 0u);
            bits |= ((((v & 0x01010101u) * 0x01020408u) >> 24) & 0xFu) << (j * 4);
        }
    } else if (mode == 1) {
        const int* p = (const int*)m + (size_t)w * 32;
#pragma unroll
        for (int j = 0; j < 32; j++) bits |= (unsigned)(p[j] != 0) << j;
    } else {
        const float* p = (const float*)m + (size_t)w * 32;
#pragma unroll
        for (int j = 0; j < 32; j++) bits |= (unsigned)(p[j] != 0.0f) << j;
    }
    out[w] = bits;
}

__global__ void conv_split_kernel(const float4* __restrict__ x,
                                  __nv_bfloat16* __restrict__ hi,
                                  __nv_bfloat16* __restrict__ lo, int n4) {
    int i = blockIdx.x * 256 + threadIdx.x;
    if (i >= n4) return;
    float4 v = x[i];
    unsigned h0, l0, h1, l1;
    split2(v.x, v.y, h0, l0);
    split2(v.z, v.w, h1, l1);
    ((uint2*)hi)[i] = make_uint2(h0, h1);
    ((uint2*)lo)[i] = make_uint2(l0, l1);
}

// ---------------- projection GEMM (mma.sync, 3-term split bf16) ------------
// mode 0: f16 single row-major out; 1: V head-transposed f16 hi/lo; 2: f32.
#define SPD 72
#define PJ_AH 0
#define PJ_AL 18432
#define PJ_BH 36864
#define PJ_BL 55296
#define PJ_SMEM 73728

__global__ void __launch_bounds__(256) proj_kernel(
    const __nv_bfloat16* __restrict__ Ah, const __nv_bfloat16* __restrict__ Al,
    const __nv_bfloat16* __restrict__ Bh, const __nv_bfloat16* __restrict__ Bl,
    float* __restrict__ Cf, __half* __restrict__ Oh, __half* __restrict__ Ol,
    int mode)
{
    extern __shared__ char smem[];
    const uint32_t sb = smem_u32(smem);
    const int tid = threadIdx.x, w = tid >> 5, lane = tid & 31;
    const int gid = lane >> 2, tig = lane & 3;
    const int m0 = blockIdx.x * 128, n0 = blockIdx.y * 128;
    const int wm = (w >> 2) * 64, wn = (w & 3) * 32;
    const int rowsel = (lane & 7) + ((lane >> 4) << 3);
    const int colsel = ((lane >> 3) & 1) * 8;

    float c[4][4][4];
#pragma unroll
    for (int mt = 0; mt < 4; mt++)
#pragma unroll
        for (int nt = 0; nt < 4; nt++)
#pragma unroll
            for (int j = 0; j < 4; j++) c[mt][nt][j] = 0.0f;

    const uint32_t aAddr = sb + ((unsigned)(wm + (lane & 15)) * SPD + (lane >> 4) * 8) * 2;
    const uint32_t bAddr4 = sb + ((unsigned)(wn + rowsel) * SPD + colsel) * 2;

    for (int kc = 0; kc < 512; kc += 64) {
#pragma unroll
        for (int it = 0; it < 4; it++) {
            int idx = it * 256 + tid, row = idx >> 3, cu = idx & 7;
            *(uint4*)(smem + PJ_AH + row * 144 + cu * 16) =
                *(const uint4*)(Ah + (size_t)(m0 + row) * 512 + kc + cu * 8);
            *(uint4*)(smem + PJ_AL + row * 144 + cu * 16) =
                *(const uint4*)(Al + (size_t)(m0 + row) * 512 + kc + cu * 8);
            *(uint4*)(smem + PJ_BH + row * 144 + cu * 16) =
                *(const uint4*)(Bh + (size_t)(n0 + row) * 512 + kc + cu * 8);
            *(uint4*)(smem + PJ_BL + row * 144 + cu * 16) =
                *(const uint4*)(Bl + (size_t)(n0 + row) * 512 + kc + cu * 8);
        }
        __syncthreads();
#pragma unroll
        for (int ks = 0; ks < 4; ks++) {
            unsigned ah[4][4], al[4][4], bh4[2][4], bl4[2][4];
#pragma unroll
            for (int mt = 0; mt < 4; mt++) {
                ldm_x4(ah[mt], aAddr + PJ_AH + (mt * 16 * SPD + ks * 16) * 2);
                ldm_x4(al[mt], aAddr + PJ_AL + (mt * 16 * SPD + ks * 16) * 2);
            }
#pragma unroll
            for (int p = 0; p < 2; p++) {
                ldm_x4(bh4[p], bAddr4 + PJ_BH + (p * 16 * SPD + ks * 16) * 2);
                ldm_x4(bl4[p], bAddr4 + PJ_BL + (p * 16 * SPD + ks * 16) * 2);
            }
#pragma unroll
            for (int mt = 0; mt < 4; mt++)
#pragma unroll
                for (int nt = 0; nt < 4; nt++) {
                    unsigned* bh = &bh4[nt >> 1][(nt & 1) * 2];
                    unsigned* bl = &bl4[nt >> 1][(nt & 1) * 2];
                    MMA(c[mt][nt], ah[mt], bh);
                    MMA(c[mt][nt], ah[mt], bl);
                    MMA(c[mt][nt], al[mt], bh);
                }
        }
        __syncthreads();
    }

    if (mode == 1) {
        float* stage = (float*)smem;  // 128 x 129 f32
#pragma unroll
        for (int mt = 0; mt < 4; mt++)
#pragma unroll
            for (int nt = 0; nt < 4; nt++) {
                int r0 = wm + mt * 16 + gid, cc0 = wn + nt * 8 + 2 * tig;
                stage[r0 * 129 + cc0] = c[mt][nt][0];
                stage[r0 * 129 + cc0 + 1] = c[mt][nt][1];
                stage[(r0 + 8) * 129 + cc0] = c[mt][nt][2];
                stage[(r0 + 8) * 129 + cc0 + 1] = c[mt][nt][3];
            }
        __syncthreads();
        const int bb = m0 >> 10, seq0 = m0 & 1023;
        const int m_local = tid & 127, nsel = tid >> 7;
#pragma unroll 8
        for (int rep = 0; rep < 64; rep++) {
            int n_local = rep * 2 + nsel;
            int n = n0 + n_local;
            int hh = n >> 6, dh = n & 63;
            size_t ob = ((size_t)((bb * 8 + hh) * 64 + dh)) * 1024 + seq0 + m_local;
            float f = stage[m_local * 129 + n_local];
            __half hv = __float2half_rn(f);
            Oh[ob] = hv;
            Ol[ob] = __float2half_rn(f - __half2float(hv));
        }
    } else if (mode == 2) {
#pragma unroll
        for (int mt = 0; mt < 4; mt++)
#pragma unroll
            for (int nt = 0; nt < 4; nt++) {
                int r0 = m0 + wm + mt * 16 + gid, cc0 = n0 + wn + nt * 8 + 2 * tig;
                *(float2*)(Cf + (size_t)r0 * 512 + cc0) =
                    make_float2(c[mt][nt][0], c[mt][nt][1]);
                *(float2*)(Cf + (size_t)(r0 + 8) * 512 + cc0) =
                    make_float2(c[mt][nt][2], c[mt][nt][3]);
            }
    } else {
        // mode 0: single f16 row-major
#pragma unroll
        for (int mt = 0; mt < 4; mt++)
#pragma unroll
            for (int nt = 0; nt < 4; nt++) {
                int r0 = m0 + wm + mt * 16 + gid, cc0 = n0 + wn + nt * 8 + 2 * tig;
                __half2 p0 = __floats2half2_rn(c[mt][nt][0], c[mt][nt][1]);
                __half2 p1 = __floats2half2_rn(c[mt][nt][2], c[mt][nt][3]);
                *(__half2*)(Oh + (size_t)r0 * 512 + cc0) = p0;
                *(__half2*)(Oh + (size_t)(r0 + 8) * 512 + cc0) = p1;
            }
    }
}

// ---------------- fused single-pass attention ----------------
// f16 single-term QK; PV = ph*vh + ph*vl (2-term). 3-stage cp.async pipeline.
// smem: sums 1024 | Q f16 18432 | 3 x (K 9216 + VH 9216 + VL 9216)
#define AT_Q 1024
#define AT_BUF0 19456
#define AT_BUFSZ 27648
#define K_OFF 0
#define VH_OFF 9216
#define VL_OFF 18432
#define AT_SMEM 102400

__global__ void __launch_bounds__(256, 2) attn_kernel(float* __restrict__ att)
{
    extern __shared__ char smem[];
    const uint32_t sb = smem_u32(smem);
    float* sums = (float*)smem;
    const int tid = threadIdx.x, w = tid >> 5, lane = tid & 31;
    const int gid = lane >> 2, tig = lane & 3;
    const int bh = blockIdx.x, b = bh >> 3, h = bh & 7;
    const int q0 = blockIdx.y * 128;
    const float SCL = 0.18033688011112042f; // 0.125 * log2(e)
    const int rowsel = (lane & 7) + ((lane >> 4) << 3);
    const int colsel = ((lane >> 3) & 1) * 8;
    const unsigned klane = ((unsigned)rowsel * SPD + colsel) * 2;

    {
        const size_t qoff = ((size_t)(b * 1024 + q0)) * 512 + h * 64;
#pragma unroll
        for (int it = 0; it < 4; it++) {
            int idx = it * 256 + tid, row = idx >> 3, cu = idx & 7;
            *(uint4*)(smem + AT_Q + row * 144 + cu * 16) =
                *(const uint4*)(g_Qf + qoff + (size_t)row * 512 + cu * 8);
        }
    }
    __syncthreads();
    unsigned aq[4][4];
    {
        const uint32_t qa = sb + AT_Q + ((unsigned)(w * 16 + (lane & 15)) * SPD + (lane >> 4) * 8) * 2;
#pragma unroll
        for (int ks = 0; ks < 4; ks++) ldm_x4(aq[ks], qa + ks * 32);
    }
    __syncthreads();

    const size_t rb0 = (size_t)(b * 1024 + q0 + w * 16 + gid) * 32;
    const size_t rb1 = rb0 + 8 * 32;
    const size_t vbase = (size_t)(bh * 64) * 1024;
    const size_t kbase = (size_t)(b * 1024) * 512 + h * 64;

    float rs0 = 0.0f, rs1 = 0.0f;
    float ctx[8][4];
#pragma unroll
    for (int dt = 0; dt < 8; dt++)
#pragma unroll
        for (int j = 0; j < 4; j++) ctx[dt][j] = 0.0f;

    float* arow0 = att ? att + ((size_t)(bh * 1024 + q0 + w * 16 + gid)) * 1024 : (float*)0;
    float* arow1 = arow0 ? arow0 + (size_t)8 * 1024 : (float*)0;

    // prologue: load chunks 0 and 1 into stages 0, 1
#pragma unroll
    for (int pc = 0; pc < 2; pc++) {
        const uint32_t kb = sb + AT_BUF0 + pc * AT_BUFSZ;
        const size_t koff = kbase + (size_t)(pc * 64) * 512;
#pragma unroll
        for (int it = 0; it < 2; it++) {
            int idx = it * 256 + tid, row = idx >> 3, cu = idx & 7;
            CP16(kb + K_OFF + row * 144 + cu * 16, g_Kf + koff + (size_t)row * 512 + cu * 8);
            CP16(kb + VH_OFF + row * 144 + cu * 16,
                 g_Vth + vbase + (size_t)row * 1024 + pc * 64 + cu * 8);
            CP16(kb + VL_OFF + row * 144 + cu * 16,
                 g_Vtl + vbase + (size_t)row * 1024 + pc * 64 + cu * 8);
        }
        CP_COMMIT();
    }

    for (int c = 0; c < 16; c++) {
        const int kc = c * 64;
        if (c < 14) {
            int nc = c + 2;
            const uint32_t kb = sb + AT_BUF0 + (nc % 3) * AT_BUFSZ;
            const size_t koff = kbase + (size_t)(nc * 64) * 512;
#pragma unroll
            for (int it = 0; it < 2; it++) {
                int idx = it * 256 + tid, row = idx >> 3, cu = idx & 7;
                CP16(kb + K_OFF + row * 144 + cu * 16, g_Kf + koff + (size_t)row * 512 + cu * 8);
                CP16(kb + VH_OFF + row * 144 + cu * 16,
                     g_Vth + vbase + (size_t)row * 1024 + nc * 64 + cu * 8);
                CP16(kb + VL_OFF + row * 144 + cu * 16,
                     g_Vtl + vbase + (size_t)row * 1024 + nc * 64 + cu * 8);
            }
            CP_COMMIT();
            CP_WAIT(2);
        } else if (c == 14) {
            CP_WAIT(1);
        } else {
            CP_WAIT(0);
        }
        __syncthreads();

        const uint32_t bb = sb + AT_BUF0 + (c % 3) * AT_BUFSZ;
        unsigned aw0[2], aw1[2], sw0[2], sw1[2];
#pragma unroll
        for (int j = 0; j < 2; j++) {
            aw0[j] = g_am[rb0 + (kc >> 5) + j];
            aw1[j] = g_am[rb1 + (kc >> 5) + j];
            sw0[j] = g_sm[rb0 + (kc >> 5) + j];
            sw1[j] = g_sm[rb1 + (kc >> 5) + j];
        }
#pragma unroll
        for (int nt2 = 0; nt2 < 4; nt2++) {
            float cc[2][4];
#pragma unroll
            for (int hh2 = 0; hh2 < 2; hh2++)
#pragma unroll
                for (int j = 0; j < 4; j++) cc[hh2][j] = 0.0f;
#pragma unroll
            for (int ks = 0; ks < 4; ks++) {
                unsigned kh4[4];
                ldm_x4(kh4, bb + K_OFF + klane + (nt2 * 16 * SPD + ks * 16) * 2);
                MMAH(cc[0], aq[ks], &kh4[0]);
                MMAH(cc[1], aq[ks], &kh4[2]);
            }
            unsigned ph[4];
#pragma unroll
            for (int half = 0; half < 2; half++) {
                int nt = nt2 * 2 + half;
                int bidx = nt * 8 + 2 * tig;
                unsigned w0 = aw0[bidx >> 5], w1 = aw1[bidx >> 5];
                unsigned s0 = sw0[bidx >> 5], s1 = sw1[bidx >> 5];
                int bo = bidx & 31;
                float t0 = cc[half][0] * SCL, t1 = cc[half][1] * SCL;
                float t2 = cc[half][2] * SCL, t3 = cc[half][3] * SCL;
                if ((w0 >> bo) & 1u) t0 = -1e30f;
                if ((w0 >> (bo + 1)) & 1u) t1 = -1e30f;
                if ((w1 >> bo) & 1u) t2 = -1e30f;
                if ((w1 >> (bo + 1)) & 1u) t3 = -1e30f;
                float p0 = fexp2(t0), p1 = fexp2(t1);
                float p2 = fexp2(t2), p3 = fexp2(t3);
                rs0 += p0 + p1;
                rs1 += p2 + p3;
                if ((s0 >> bo) & 1u) p0 = 0.0f;
                if ((s0 >> (bo + 1)) & 1u) p1 = 0.0f;
                if ((s1 >> bo) & 1u) p2 = 0.0f;
                if ((s1 >> (bo + 1)) & 1u) p3 = 0.0f;
                if (arow0) {
                    *(float2*)(arow0 + kc + bidx) = make_float2(p0, p1);
                    *(float2*)(arow1 + kc + bidx) = make_float2(p2, p3);
                }
                ph[half * 2] = packh2(p0, p1);
                ph[half * 2 + 1] = packh2(p2, p3);
            }
#pragma unroll
            for (int dt2 = 0; dt2 < 4; dt2++) {
                unsigned bvh[4], bvl[4];
                ldm_x4(bvh, bb + VH_OFF + klane + (dt2 * 16 * SPD + nt2 * 16) * 2);
                ldm_x4(bvl, bb + VL_OFF + klane + (dt2 * 16 * SPD + nt2 * 16) * 2);
                MMAH(ctx[dt2 * 2], ph, &bvh[0]);
                MMAH(ctx[dt2 * 2], ph, &bvl[0]);
                MMAH(ctx[dt2 * 2 + 1], ph, &bvh[2]);
                MMAH(ctx[dt2 * 2 + 1], ph, &bvl[2]);
            }
        }
        __syncthreads();
    }

    rs0 += __shfl_xor_sync(0xffffffffu, rs0, 1);
    rs0 += __shfl_xor_sync(0xffffffffu, rs0, 2);
    rs1 += __shfl_xor_sync(0xffffffffu, rs1, 1);
    rs1 += __shfl_xor_sync(0xffffffffu, rs1, 2);
    if (tig == 0) {
        sums[w * 16 + gid] = rs0;
        sums[w * 16 + gid + 8] = rs1;
    }
    __syncthreads();
    if (tid < 128) sums[tid] = 1.0f / sums[tid];
    __syncthreads();
    const float inv0 = sums[w * 16 + gid];
    const float inv1 = sums[w * 16 + gid + 8];

    // ctx epilogue (normalized, bf16 hi/lo for Wo projection)
    {
        size_t r0 = (size_t)(b * 1024 + q0 + w * 16 + gid) * 512 + h * 64;
        size_t r1 = r0 + (size_t)8 * 512;
#pragma unroll
        for (int dt = 0; dt < 8; dt++) {
            int cc0 = dt * 8 + 2 * tig;
            unsigned hp, lp;
            split2(ctx[dt][0] * inv0, ctx[dt][1] * inv0, hp, lp);
            *(unsigned*)(g_Ch + r0 + cc0) = hp;
            *(unsigned*)(g_Cl + r0 + cc0) = lp;
            split2(ctx[dt][2] * inv1, ctx[dt][3] * inv1, hp, lp);
            *(unsigned*)(g_Ch + r1 + cc0) = hp;
            *(unsigned*)(g_Cl + r1 + cc0) = lp;
        }
    }

    // self-normalize this CTA's att rows
    if (att) {
        float4* ab = (float4*)(att + ((size_t)(bh * 1024 + q0)) * 1024);
#pragma unroll 4
        for (int i = tid; i < 128 * 256; i += 256) {
            float s = sums[i >> 8];
            float4 v = ab[i];
            v.x *= s; v.y *= s; v.z *= s; v.w *= s;
            ab[i] = v;
        }
    }
}

// ---------------- residual + LayerNorm ----------------
__global__ void __launch_bounds__(256) ln_kernel(
    const float* __restrict__ proj, const float* __restrict__ res,
    float* __restrict__ out)
{
    __shared__ float reds[8], redq[8];
    const int row = blockIdx.x, tid = threadIdx.x;
    const float* p = proj + (size_t)row * ND;
    const float* rr = res + (size_t)row * ND;
    float x0 = rr[tid] + p[tid];
    float x1 = rr[tid + 256] + p[tid + 256];
    float s = x0 + x1, q = x0 * x0 + x1 * x1;
#pragma unroll
    for (int o = 16; o > 0; o >>= 1) {
        s += __shfl_xor_sync(0xffffffffu, s, o);
        q += __shfl_xor_sync(0xffffffffu, q, o);
    }
    if ((tid & 31) == 0) { reds[tid >> 5] = s; redq[tid >> 5] = q; }
    __syncthreads();
    float ts = 0, tq = 0;
#pragma unroll
    for (int i = 0; i < 8; i++) { ts += reds[i]; tq += redq[i]; }
    float mean = ts * (1.0f / ND);
    float var = tq * (1.0f / ND) - mean * mean;
    float rsv = rsqrtf(var + 1e-5f);
    out[(size_t)row * ND + tid] = (x0 - mean) * rsv;
    out[(size_t)row * ND + tid + 256] = (x1 - mean) * rsv;
}

// ---------------------------------------------------------------------------
extern "C" void kernel_launch(void* const* d_in, const int* in_sizes, int n_in,
                              void* d_out, int out_size)
{
    const float* query = (const float*)d_in[0];
    const float* key   = (const float*)d_in[1];
    const float* value = (const float*)d_in[2];
    const void*  amask = d_in[3];
    const void*  smask = d_in[4];
    const float* Wq = (const float*)d_in[5];
    const float* Wk = (const float*)d_in[6];
    const float* Wv = (const float*)d_in[7];
    const float* Wo = (const float*)d_in[8];

    float* out = (float*)d_out;
    float* att = ((size_t)out_size >= ACT_ELEMS + ATT_ELEMS) ? out + ACT_ELEMS : (float*)0;

    void *pQAh,*pQAl,*pKAh,*pKAl,*pVAh,*pVAl;
    void *pWQh,*pWQl,*pWKh,*pWKl,*pWVh,*pWVl,*pWOh,*pWOl;
    void *pQf,*pKf,*pVth,*pVtl,*pCh,*pCl,*pPf,*pAm,*pSm;
    cudaGetSymbolAddress(&pQAh, g_QAh); cudaGetSymbolAddress(&pQAl, g_QAl);
    cudaGetSymbolAddress(&pKAh, g_KAh); cudaGetSymbolAddress(&pKAl, g_KAl);
    cudaGetSymbolAddress(&pVAh, g_VAh); cudaGetSymbolAddress(&pVAl, g_VAl);
    cudaGetSymbolAddress(&pWQh, g_WQh); cudaGetSymbolAddress(&pWQl, g_WQl);
    cudaGetSymbolAddress(&pWKh, g_WKh); cudaGetSymbolAddress(&pWKl, g_WKl);
    cudaGetSymbolAddress(&pWVh, g_WVh); cudaGetSymbolAddress(&pWVl, g_WVl);
    cudaGetSymbolAddress(&pWOh, g_WOh); cudaGetSymbolAddress(&pWOl, g_WOl);
    cudaGetSymbolAddress(&pQf, g_Qf);   cudaGetSymbolAddress(&pKf, g_Kf);
    cudaGetSymbolAddress(&pVth, g_Vth); cudaGetSymbolAddress(&pVtl, g_Vtl);
    cudaGetSymbolAddress(&pCh, g_Ch);   cudaGetSymbolAddress(&pCl, g_Cl);
    cudaGetSymbolAddress(&pPf, g_projf);
    cudaGetSymbolAddress(&pAm, g_am);   cudaGetSymbolAddress(&pSm, g_sm);

    cudaFuncSetAttribute(proj_kernel, cudaFuncAttributeMaxDynamicSharedMemorySize, PJ_SMEM);
    cudaFuncSetAttribute(attn_kernel, cudaFuncAttributeMaxDynamicSharedMemorySize, AT_SMEM);

    cudaStream_t s1, s2, s3;
    cudaEvent_t evA, evB, evK, evV;
    cudaStreamCreateWithFlags(&s1, cudaStreamNonBlocking);
    cudaStreamCreateWithFlags(&s2, cudaStreamNonBlocking);
    cudaStreamCreateWithFlags(&s3, cudaStreamNonBlocking);
    cudaEventCreateWithFlags(&evA, cudaEventDisableTiming);
    cudaEventCreateWithFlags(&evB, cudaEventDisableTiming);
    cudaEventCreateWithFlags(&evK, cudaEventDisableTiming);
    cudaEventCreateWithFlags(&evV, cudaEventDisableTiming);

    const int nA4 = (int)(ACT_ELEMS / 4), nW4 = (int)(W_ELEMS / 4);
    dim3 pgrid(TOK / 128, ND / 128);

    detect_mask_kernel<<<1, 256>>>((const unsigned*)amask);
    cudaEventRecord(evA, 0);

    // s1: masks + Wo conversion
    cudaStreamWaitEvent(s1, evA, 0);
    pack_mask_kernel<<<MASK_WORDS / 256, 256, 0, s1>>>(amask, (unsigned*)pAm);
    pack_mask_kernel<<<MASK_WORDS / 256, 256, 0, s1>>>(smask, (unsigned*)pSm);
    conv_split_kernel<<<nW4 / 256, 256, 0, s1>>>((const float4*)Wo,
        (__nv_bfloat16*)pWOh, (__nv_bfloat16*)pWOl, nW4);
    cudaEventRecord(evB, s1);

    // s2: K pipeline
    cudaStreamWaitEvent(s2, evA, 0);
    conv_split_kernel<<<nA4 / 256, 256, 0, s2>>>((const float4*)key,
        (__nv_bfloat16*)pKAh, (__nv_bfloat16*)pKAl, nA4);
    conv_split_kernel<<<nW4 / 256, 256, 0, s2>>>((const float4*)Wk,
        (__nv_bfloat16*)pWKh, (__nv_bfloat16*)pWKl, nW4);
    proj_kernel<<<pgrid, 256, PJ_SMEM, s2>>>((const __nv_bfloat16*)pKAh, (const __nv_bfloat16*)pKAl,
        (const __nv_bfloat16*)pWKh, (const __nv_bfloat16*)pWKl,
        (float*)0, (__half*)pKf, (__half*)0, 0);
    cudaEventRecord(evK, s2);

    // s3: V pipeline
    cudaStreamWaitEvent(s3, evA, 0);
    conv_split_kernel<<<nA4 / 256, 256, 0, s3>>>((const float4*)value,
        (__nv_bfloat16*)pVAh, (__nv_bfloat16*)pVAl, nA4);
    conv_split_kernel<<<nW4 / 256, 256, 0, s3>>>((const float4*)Wv,
        (__nv_bfloat16*)pWVh, (__nv_bfloat16*)pWVl, nW4);
    proj_kernel<<<pgrid, 256, PJ_SMEM, s3>>>((const __nv_bfloat16*)pVAh, (const __nv_bfloat16*)pVAl,
        (const __nv_bfloat16*)pWVh, (const __nv_bfloat16*)pWVl,
        (float*)0, (__half*)pVth, (__half*)pVtl, 1);
    cudaEventRecord(evV, s3);

    // main: Q pipeline
    conv_split_kernel<<<nA4 / 256, 256>>>((const float4*)query,
        (__nv_bfloat16*)pQAh, (__nv_bfloat16*)pQAl, nA4);
    conv_split_kernel<<<nW4 / 256, 256>>>((const float4*)Wq,
        (__nv_bfloat16*)pWQh, (__nv_bfloat16*)pWQl, nW4);
    proj_kernel<<<pgrid, 256, PJ_SMEM>>>((const __nv_bfloat16*)pQAh, (const __nv_bfloat16*)pQAl,
        (const __nv_bfloat16*)pWQh, (const __nv_bfloat16*)pWQl,
        (float*)0, (__half*)pQf, (__half*)0, 0);

    cudaStreamWaitEvent(0, evB, 0);
    cudaStreamWaitEvent(0, evK, 0);
    cudaStreamWaitEvent(0, evV, 0);
    attn_kernel<<<dim3(NB * NH, NL / 128), 256, AT_SMEM>>>(att);

    proj_kernel<<<pgrid, 256, PJ_SMEM>>>((const __nv_bfloat16*)pCh, (const __nv_bfloat16*)pCl,
        (const __nv_bfloat16*)pWOh, (const __nv_bfloat16*)pWOl,
        (float*)pPf, (__half*)0, (__half*)0, 2);
    ln_kernel<<<TOK, 256>>>((const float*)pPf, query, out);

    cudaEventDestroy(evA); cudaEventDestroy(evB);
    cudaEventDestroy(evK); cudaEventDestroy(evV);
    cudaStreamDestroy(s1); cudaStreamDestroy(s2); cudaStreamDestroy(s3);
}

// round 14
// speedup vs baseline: 1.0272x; 1.0272x over previous
#include <cuda_runtime.h>
#include <cuda_bf16.h>
#include <cuda_fp16.h>
#include <math.h>
#include <stdint.h>

#define NB 8
#define NL 1024
#define ND 512
#define NH 8
#define NDH 64
#define TOK (NB * NL)
#define ACT_ELEMS ((size_t)TOK * ND)
#define W_ELEMS ((size_t)ND * ND)
#define ATT_ELEMS ((size_t)NB * NH * NL * NL)
#define MASK_WORDS (ATT_ELEMS / 32)

// per-path staging buffers (no false deps between Q/K/V pipelines)
__device__ __nv_bfloat16 g_QAh[ACT_ELEMS], g_QAl[ACT_ELEMS];
__device__ __nv_bfloat16 g_KAh[ACT_ELEMS], g_KAl[ACT_ELEMS];
__device__ __nv_bfloat16 g_VAh[ACT_ELEMS], g_VAl[ACT_ELEMS];
__device__ __nv_bfloat16 g_WQh[W_ELEMS], g_WQl[W_ELEMS];
__device__ __nv_bfloat16 g_WKh[W_ELEMS], g_WKl[W_ELEMS];
__device__ __nv_bfloat16 g_WVh[W_ELEMS], g_WVl[W_ELEMS];
__device__ __nv_bfloat16 g_WOh[W_ELEMS], g_WOl[W_ELEMS];
__device__ __half       g_Qf[ACT_ELEMS], g_Kf[ACT_ELEMS];     // single f16
__device__ __half       g_Vth[ACT_ELEMS], g_Vtl[ACT_ELEMS];   // [bh*64+d][1024] f16 hi/lo
__device__ __nv_bfloat16 g_Ch[ACT_ELEMS], g_Cl[ACT_ELEMS];
__device__ float        g_projf[ACT_ELEMS];
__device__ unsigned     g_am[MASK_WORDS], g_sm[MASK_WORDS];
__device__ int          g_mask_mode;

// ---------------- helpers ----------------
__device__ __forceinline__ uint32_t smem_u32(const void* p) {
    uint32_t a;
    asm("{ .reg .u64 t; cvta.to.shared.u64 t, %1; cvt.u32.u64 %0, t; }" : "=r"(a) : "l"(p));
    return a;
}
__device__ __forceinline__ void ldm_x4(unsigned r[4], uint32_t a) {
    asm volatile("ldmatrix.sync.aligned.m8n8.x4.shared.b16 {%0,%1,%2,%3}, [%4];"
                 : "=r"(r[0]), "=r"(r[1]), "=r"(r[2]), "=r"(r[3]) : "r"(a) : "memory");
}
#define MMA(c, a, b) \
    asm volatile("mma.sync.aligned.m16n8k16.row.col.f32.bf16.bf16.f32 " \
                 "{%0,%1,%2,%3},{%4,%5,%6,%7},{%8,%9},{%0,%1,%2,%3};" \
                 : "+f"((c)[0]), "+f"((c)[1]), "+f"((c)[2]), "+f"((c)[3]) \
                 : "r"((a)[0]), "r"((a)[1]), "r"((a)[2]), "r"((a)[3]), \
                   "r"((b)[0]), "r"((b)[1]))
#define MMAH(c, a, b) \
    asm volatile("mma.sync.aligned.m16n8k16.row.col.f32.f16.f16.f32 " \
                 "{%0,%1,%2,%3},{%4,%5,%6,%7},{%8,%9},{%0,%1,%2,%3};" \
                 : "+f"((c)[0]), "+f"((c)[1]), "+f"((c)[2]), "+f"((c)[3]) \
                 : "r"((a)[0]), "r"((a)[1]), "r"((a)[2]), "r"((a)[3]), \
                   "r"((b)[0]), "r"((b)[1]))

#define CP16(dst, src) \
    asm volatile("cp.async.cg.shared.global [%0], [%1], 16;" :: "r"(dst), "l"(src) : "memory")
#define CP_COMMIT() asm volatile("cp.async.commit_group;" ::: "memory")
#define CP_WAIT(n)  asm volatile("cp.async.wait_group %0;" :: "n"(n) : "memory")

__device__ __forceinline__ void split2(float f0, float f1, unsigned& hp, unsigned& lp) {
    __nv_bfloat16 h0 = __float2bfloat16_rn(f0), h1 = __float2bfloat16_rn(f1);
    __nv_bfloat16 l0 = __float2bfloat16_rn(f0 - __bfloat162float(h0));
    __nv_bfloat16 l1 = __float2bfloat16_rn(f1 - __bfloat162float(h1));
    hp = (unsigned)__bfloat16_as_ushort(h0) | ((unsigned)__bfloat16_as_ushort(h1) << 16);
    lp = (unsigned)__bfloat16_as_ushort(l0) | ((unsigned)__bfloat16_as_ushort(l1) << 16);
}
__device__ __forceinline__ unsigned packh2(float f0, float f1) {
    __half2 h = __floats2half2_rn(f0, f1);
    return *(unsigned*)&h;
}

// degree-4 exp2 on fma pipe; rel err ~3e-6
__device__ __forceinline__ float fexp2(float x) {
    x = fmaxf(fminf(x, 120.0f), -126.0f);
    float fl = floorf(x);
    float f = x - fl;
    float p = 1.35557472e-2f;
    p = fmaf(p, f, 5.20323690e-2f);
    p = fmaf(p, f, 2.41379774e-1f);
    p = fmaf(p, f, 6.93018210e-1f);
    p = fmaf(p, f, 1.00000370f);
    return __int_as_float(__float_as_int(p) + (((int)fl) << 23));
}

// ---------------- prep kernels ----------------
__global__ void detect_mask_kernel(const unsigned* __restrict__ m) {
    __shared__ int f32flag, u8flag;
    if (threadIdx.x == 0) { f32flag = 0; u8flag = 0; }
    __syncthreads();
    int lf = 0, lu = 0;
    for (int i = threadIdx.x; i < 4096; i += blockDim.x) {
        unsigned w = m[i];
        if (w == 0x3f800000u) lf = 1;
        else if (w > 1u) lu = 1;
    }
    if (lf) atomicOr(&f32flag, 1);
    if (lu) atomicOr(&u8flag, 1);
    __syncthreads();
    if (threadIdx.x == 0) g_mask_mode = f32flag ? 2 : (u8flag ? 0 : 1);
}

__global__ void pack_mask_kernel(const void* __restrict__ m, unsigned* __restrict__ out) {
    int w = blockIdx.x * 256 + threadIdx.x;
    if (w >= (int)MASK_WORDS) return;
    int mode = g_mask_mode;
    unsigned bits = 0;
    if (mode == 0) {
        const unsigned* p = (const unsigned*)m + (size_t)w * 8;
#pragma unroll
        for (int j = 0; j < 8; j++) {
            unsigned v = __vcmpne4(p[j], 0u);
            bits |= ((((v & 0x01010101u) * 0x01020408u) >> 24) & 0xFu) << (j * 4);
        }
    } else if (mode == 1) {
        const int* p = (const int*)m + (size_t)w * 32;
#pragma unroll
        for (int j = 0; j < 32; j++) bits |= (unsigned)(p[j] != 0) << j;
    } else {
        const float* p = (const float*)m + (size_t)w * 32;
#pragma unroll
        for (int j = 0; j < 32; j++) bits |= (unsigned)(p[j] != 0.0f) << j;
    }
    out[w] = bits;
}

__global__ void conv_split_kernel(const float4* __restrict__ x,
                                  __nv_bfloat16* __restrict__ hi,
                                  __nv_bfloat16* __restrict__ lo, int n4) {
    int i = blockIdx.x * 256 + threadIdx.x;
    if (i >= n4) return;
    float4 v = x[i];
    unsigned h0, l0, h1, l1;
    split2(v.x, v.y, h0, l0);
    split2(v.z, v.w, h1, l1);
    ((uint2*)hi)[i] = make_uint2(h0, h1);
    ((uint2*)lo)[i] = make_uint2(l0, l1);
}

// ---------------- projection GEMM (mma.sync, 3-term split bf16) ------------
// mode 0: f16 single row-major out; 1: V head-transposed f16 hi/lo; 2: f32.
#define SPD 72
#define PJ_AH 0
#define PJ_AL 18432
#define PJ_BH 36864
#define PJ_BL 55296
#define PJ_SMEM 73728

__global__ void __launch_bounds__(256) proj_kernel(
    const __nv_bfloat16* __restrict__ Ah, const __nv_bfloat16* __restrict__ Al,
    const __nv_bfloat16* __restrict__ Bh, const __nv_bfloat16* __restrict__ Bl,
    float* __restrict__ Cf, __half* __restrict__ Oh, __half* __restrict__ Ol,
    int mode)
{
    extern __shared__ char smem[];
    const uint32_t sb = smem_u32(smem);
    const int tid = threadIdx.x, w = tid >> 5, lane = tid & 31;
    const int gid = lane >> 2, tig = lane & 3;
    const int m0 = blockIdx.x * 128, n0 = blockIdx.y * 128;
    const int wm = (w >> 2) * 64, wn = (w & 3) * 32;
    const int rowsel = (lane & 7) + ((lane >> 4) << 3);
    const int colsel = ((lane >> 3) & 1) * 8;

    float c[4][4][4];
#pragma unroll
    for (int mt = 0; mt < 4; mt++)
#pragma unroll
        for (int nt = 0; nt < 4; nt++)
#pragma unroll
            for (int j = 0; j < 4; j++) c[mt][nt][j] = 0.0f;

    const uint32_t aAddr = sb + ((unsigned)(wm + (lane & 15)) * SPD + (lane >> 4) * 8) * 2;
    const uint32_t bAddr4 = sb + ((unsigned)(wn + rowsel) * SPD + colsel) * 2;

    for (int kc = 0; kc < 512; kc += 64) {
#pragma unroll
        for (int it = 0; it < 4; it++) {
            int idx = it * 256 + tid, row = idx >> 3, cu = idx & 7;
            *(uint4*)(smem + PJ_AH + row * 144 + cu * 16) =
                *(const uint4*)(Ah + (size_t)(m0 + row) * 512 + kc + cu * 8);
            *(uint4*)(smem + PJ_AL + row * 144 + cu * 16) =
                *(const uint4*)(Al + (size_t)(m0 + row) * 512 + kc + cu * 8);
            *(uint4*)(smem + PJ_BH + row * 144 + cu * 16) =
                *(const uint4*)(Bh + (size_t)(n0 + row) * 512 + kc + cu * 8);
            *(uint4*)(smem + PJ_BL + row * 144 + cu * 16) =
                *(const uint4*)(Bl + (size_t)(n0 + row) * 512 + kc + cu * 8);
        }
        __syncthreads();
#pragma unroll
        for (int ks = 0; ks < 4; ks++) {
            unsigned ah[4][4], al[4][4], bh4[2][4], bl4[2][4];
#pragma unroll
            for (int mt = 0; mt < 4; mt++) {
                ldm_x4(ah[mt], aAddr + PJ_AH + (mt * 16 * SPD + ks * 16) * 2);
                ldm_x4(al[mt], aAddr + PJ_AL + (mt * 16 * SPD + ks * 16) * 2);
            }
#pragma unroll
            for (int p = 0; p < 2; p++) {
                ldm_x4(bh4[p], bAddr4 + PJ_BH + (p * 16 * SPD + ks * 16) * 2);
                ldm_x4(bl4[p], bAddr4 + PJ_BL + (p * 16 * SPD + ks * 16) * 2);
            }
#pragma unroll
            for (int mt = 0; mt < 4; mt++)
#pragma unroll
                for (int nt = 0; nt < 4; nt++) {
                    unsigned* bh = &bh4[nt >> 1][(nt & 1) * 2];
                    unsigned* bl = &bl4[nt >> 1][(nt & 1) * 2];
                    MMA(c[mt][nt], ah[mt], bh);
                    MMA(c[mt][nt], ah[mt], bl);
                    MMA(c[mt][nt], al[mt], bh);
                }
        }
        __syncthreads();
    }

    if (mode == 1) {
        float* stage = (float*)smem;  // 128 x 129 f32
#pragma unroll
        for (int mt = 0; mt < 4; mt++)
#pragma unroll
            for (int nt = 0; nt < 4; nt++) {
                int r0 = wm + mt * 16 + gid, cc0 = wn + nt * 8 + 2 * tig;
                stage[r0 * 129 + cc0] = c[mt][nt][0];
                stage[r0 * 129 + cc0 + 1] = c[mt][nt][1];
                stage[(r0 + 8) * 129 + cc0] = c[mt][nt][2];
                stage[(r0 + 8) * 129 + cc0 + 1] = c[mt][nt][3];
            }
        __syncthreads();
        const int bb = m0 >> 10, seq0 = m0 & 1023;
        const int m_local = tid & 127, nsel = tid >> 7;
#pragma unroll 8
        for (int rep = 0; rep < 64; rep++) {
            int n_local = rep * 2 + nsel;
            int n = n0 + n_local;
            int hh = n >> 6, dh = n & 63;
            size_t ob = ((size_t)((bb * 8 + hh) * 64 + dh)) * 1024 + seq0 + m_local;
            float f = stage[m_local * 129 + n_local];
            __half hv = __float2half_rn(f);
            Oh[ob] = hv;
            Ol[ob] = __float2half_rn(f - __half2float(hv));
        }
    } else if (mode == 2) {
#pragma unroll
        for (int mt = 0; mt < 4; mt++)
#pragma unroll
            for (int nt = 0; nt < 4; nt++) {
                int r0 = m0 + wm + mt * 16 + gid, cc0 = n0 + wn + nt * 8 + 2 * tig;
                *(float2*)(Cf + (size_t)r0 * 512 + cc0) =
                    make_float2(c[mt][nt][0], c[mt][nt][1]);
                *(float2*)(Cf + (size_t)(r0 + 8) * 512 + cc0) =
                    make_float2(c[mt][nt][2], c[mt][nt][3]);
            }
    } else {
        // mode 0: single f16 row-major
#pragma unroll
        for (int mt = 0; mt < 4; mt++)
#pragma unroll
            for (int nt = 0; nt < 4; nt++) {
                int r0 = m0 + wm + mt * 16 + gid, cc0 = n0 + wn + nt * 8 + 2 * tig;
                __half2 p0 = __floats2half2_rn(c[mt][nt][0], c[mt][nt][1]);
                __half2 p1 = __floats2half2_rn(c[mt][nt][2], c[mt][nt][3]);
                *(__half2*)(Oh + (size_t)r0 * 512 + cc0) = p0;
                *(__half2*)(Oh + (size_t)(r0 + 8) * 512 + cc0) = p1;
            }
    }
}

// ---------------- fused single-pass attention ----------------
// f16 single-term QK; PV = ph*vh + ph*vl (2-term). 2-stage cp.async pipeline.
// smem: sums 1024 | Q f16 18432 | 2 x (K 9216 + VH 9216 + VL 9216)
#define AT_Q 1024
#define AT_BUF0 19456
#define AT_BUFSZ 27648
#define K_OFF 0
#define VH_OFF 9216
#define VL_OFF 18432
#define AT_SMEM 74752

__global__ void __launch_bounds__(256, 2) attn_kernel(float* __restrict__ att)
{
    extern __shared__ char smem[];
    const uint32_t sb = smem_u32(smem);
    float* sums = (float*)smem;
    const int tid = threadIdx.x, w = tid >> 5, lane = tid & 31;
    const int gid = lane >> 2, tig = lane & 3;
    const int bh = blockIdx.x, b = bh >> 3, h = bh & 7;
    const int q0 = blockIdx.y * 128;
    const float SCL = 0.18033688011112042f; // 0.125 * log2(e)
    const int rowsel = (lane & 7) + ((lane >> 4) << 3);
    const int colsel = ((lane >> 3) & 1) * 8;
    const unsigned klane = ((unsigned)rowsel * SPD + colsel) * 2;

    {
        const size_t qoff = ((size_t)(b * 1024 + q0)) * 512 + h * 64;
#pragma unroll
        for (int it = 0; it < 4; it++) {
            int idx = it * 256 + tid, row = idx >> 3, cu = idx & 7;
            *(uint4*)(smem + AT_Q + row * 144 + cu * 16) =
                *(const uint4*)(g_Qf + qoff + (size_t)row * 512 + cu * 8);
        }
    }
    __syncthreads();
    unsigned aq[4][4];
    {
        const uint32_t qa = sb + AT_Q + ((unsigned)(w * 16 + (lane & 15)) * SPD + (lane >> 4) * 8) * 2;
#pragma unroll
        for (int ks = 0; ks < 4; ks++) ldm_x4(aq[ks], qa + ks * 32);
    }
    __syncthreads();

    const size_t rb0 = (size_t)(b * 1024 + q0 + w * 16 + gid) * 32;
    const size_t rb1 = rb0 + 8 * 32;
    const size_t vbase = (size_t)(bh * 64) * 1024;
    const size_t kbase = (size_t)(b * 1024) * 512 + h * 64;

    float rs0 = 0.0f, rs1 = 0.0f;
    float ctx[8][4];
#pragma unroll
    for (int dt = 0; dt < 8; dt++)
#pragma unroll
        for (int j = 0; j < 4; j++) ctx[dt][j] = 0.0f;

    float* arow0 = att ? att + ((size_t)(bh * 1024 + q0 + w * 16 + gid)) * 1024 : (float*)0;
    float* arow1 = arow0 ? arow0 + (size_t)8 * 1024 : (float*)0;

    // prologue: chunk 0
    {
        const uint32_t kb = sb + AT_BUF0;
#pragma unroll
        for (int it = 0; it < 2; it++) {
            int idx = it * 256 + tid, row = idx >> 3, cu = idx & 7;
            CP16(kb + K_OFF + row * 144 + cu * 16, g_Kf + kbase + (size_t)row * 512 + cu * 8);
            CP16(kb + VH_OFF + row * 144 + cu * 16, g_Vth + vbase + (size_t)row * 1024 + cu * 8);
            CP16(kb + VL_OFF + row * 144 + cu * 16, g_Vtl + vbase + (size_t)row * 1024 + cu * 8);
        }
        CP_COMMIT();
    }

    for (int c = 0; c < 16; c++) {
        const int kc = c * 64;
        if (c < 15) {
            const uint32_t kb = sb + AT_BUF0 + ((c + 1) & 1) * AT_BUFSZ;
            const size_t koff = kbase + (size_t)(kc + 64) * 512;
#pragma unroll
            for (int it = 0; it < 2; it++) {
                int idx = it * 256 + tid, row = idx >> 3, cu = idx & 7;
                CP16(kb + K_OFF + row * 144 + cu * 16, g_Kf + koff + (size_t)row * 512 + cu * 8);
                CP16(kb + VH_OFF + row * 144 + cu * 16,
                     g_Vth + vbase + (size_t)row * 1024 + kc + 64 + cu * 8);
                CP16(kb + VL_OFF + row * 144 + cu * 16,
                     g_Vtl + vbase + (size_t)row * 1024 + kc + 64 + cu * 8);
            }
            CP_COMMIT();
            CP_WAIT(1);
        } else {
            CP_WAIT(0);
        }
        __syncthreads();

        const uint32_t bb = sb + AT_BUF0 + (c & 1) * AT_BUFSZ;
        unsigned aw0[2], aw1[2], sw0[2], sw1[2];
#pragma unroll
        for (int j = 0; j < 2; j++) {
            aw0[j] = g_am[rb0 + (kc >> 5) + j];
            aw1[j] = g_am[rb1 + (kc >> 5) + j];
            sw0[j] = g_sm[rb0 + (kc >> 5) + j];
            sw1[j] = g_sm[rb1 + (kc >> 5) + j];
        }
#pragma unroll
        for (int nt2 = 0; nt2 < 4; nt2++) {
            float cc[2][4];
#pragma unroll
            for (int hh2 = 0; hh2 < 2; hh2++)
#pragma unroll
                for (int j = 0; j < 4; j++) cc[hh2][j] = 0.0f;
#pragma unroll
            for (int ks = 0; ks < 4; ks++) {
                unsigned kh4[4];
                ldm_x4(kh4, bb + K_OFF + klane + (nt2 * 16 * SPD + ks * 16) * 2);
                MMAH(cc[0], aq[ks], &kh4[0]);
                MMAH(cc[1], aq[ks], &kh4[2]);
            }
            unsigned ph[4];
#pragma unroll
            for (int half = 0; half < 2; half++) {
                int nt = nt2 * 2 + half;
                int bidx = nt * 8 + 2 * tig;
                unsigned w0 = aw0[bidx >> 5], w1 = aw1[bidx >> 5];
                unsigned s0 = sw0[bidx >> 5], s1 = sw1[bidx >> 5];
                int bo = bidx & 31;
                float t0 = cc[half][0] * SCL, t1 = cc[half][1] * SCL;
                float t2 = cc[half][2] * SCL, t3 = cc[half][3] * SCL;
                if ((w0 >> bo) & 1u) t0 = -1e30f;
                if ((w0 >> (bo + 1)) & 1u) t1 = -1e30f;
                if ((w1 >> bo) & 1u) t2 = -1e30f;
                if ((w1 >> (bo + 1)) & 1u) t3 = -1e30f;
                float p0 = fexp2(t0), p1 = fexp2(t1);
                float p2 = fexp2(t2), p3 = fexp2(t3);
                rs0 += p0 + p1;
                rs1 += p2 + p3;
                if ((s0 >> bo) & 1u) p0 = 0.0f;
                if ((s0 >> (bo + 1)) & 1u) p1 = 0.0f;
                if ((s1 >> bo) & 1u) p2 = 0.0f;
                if ((s1 >> (bo + 1)) & 1u) p3 = 0.0f;
                if (arow0) {
                    *(float2*)(arow0 + kc + bidx) = make_float2(p0, p1);
                    *(float2*)(arow1 + kc + bidx) = make_float2(p2, p3);
                }
                ph[half * 2] = packh2(p0, p1);
                ph[half * 2 + 1] = packh2(p2, p3);
            }
#pragma unroll
            for (int dt2 = 0; dt2 < 4; dt2++) {
                unsigned bvh[4], bvl[4];
                ldm_x4(bvh, bb + VH_OFF + klane + (dt2 * 16 * SPD + nt2 * 16) * 2);
                ldm_x4(bvl, bb + VL_OFF + klane + (dt2 * 16 * SPD + nt2 * 16) * 2);
                MMAH(ctx[dt2 * 2], ph, &bvh[0]);
                MMAH(ctx[dt2 * 2], ph, &bvl[0]);
                MMAH(ctx[dt2 * 2 + 1], ph, &bvh[2]);
                MMAH(ctx[dt2 * 2 + 1], ph, &bvl[2]);
            }
        }
        __syncthreads();
    }

    rs0 += __shfl_xor_sync(0xffffffffu, rs0, 1);
    rs0 += __shfl_xor_sync(0xffffffffu, rs0, 2);
    rs1 += __shfl_xor_sync(0xffffffffu, rs1, 1);
    rs1 += __shfl_xor_sync(0xffffffffu, rs1, 2);
    if (tig == 0) {
        sums[w * 16 + gid] = rs0;
        sums[w * 16 + gid + 8] = rs1;
    }
    __syncthreads();
    if (tid < 128) sums[tid] = 1.0f / sums[tid];
    __syncthreads();
    const float inv0 = sums[w * 16 + gid];
    const float inv1 = sums[w * 16 + gid + 8];

    // ctx epilogue (normalized, bf16 hi/lo for Wo projection)
    {
        size_t r0 = (size_t)(b * 1024 + q0 + w * 16 + gid) * 512 + h * 64;
        size_t r1 = r0 + (size_t)8 * 512;
#pragma unroll
        for (int dt = 0; dt < 8; dt++) {
            int cc0 = dt * 8 + 2 * tig;
            unsigned hp, lp;
            split2(ctx[dt][0] * inv0, ctx[dt][1] * inv0, hp, lp);
            *(unsigned*)(g_Ch + r0 + cc0) = hp;
            *(unsigned*)(g_Cl + r0 + cc0) = lp;
            split2(ctx[dt][2] * inv1, ctx[dt][3] * inv1, hp, lp);
            *(unsigned*)(g_Ch + r1 + cc0) = hp;
            *(unsigned*)(g_Cl + r1 + cc0) = lp;
        }
    }

    // self-normalize this CTA's att rows
    if (att) {
        float4* ab = (float4*)(att + ((size_t)(bh * 1024 + q0)) * 1024);
#pragma unroll 4
        for (int i = tid; i < 128 * 256; i += 256) {
            float s = sums[i >> 8];
            float4 v = ab[i];
            v.x *= s; v.y *= s; v.z *= s; v.w *= s;
            ab[i] = v;
        }
    }
}

// ---------------- residual + LayerNorm ----------------
__global__ void __launch_bounds__(256) ln_kernel(
    const float* __restrict__ proj, const float* __restrict__ res,
    float* __restrict__ out)
{
    __shared__ float reds[8], redq[8];
    const int row = blockIdx.x, tid = threadIdx.x;
    const float* p = proj + (size_t)row * ND;
    const float* rr = res + (size_t)row * ND;
    float x0 = rr[tid] + p[tid];
    float x1 = rr[tid + 256] + p[tid + 256];
    float s = x0 + x1, q = x0 * x0 + x1 * x1;
#pragma unroll
    for (int o = 16; o > 0; o >>= 1) {
        s += __shfl_xor_sync(0xffffffffu, s, o);
        q += __shfl_xor_sync(0xffffffffu, q, o);
    }
    if ((tid & 31) == 0) { reds[tid >> 5] = s; redq[tid >> 5] = q; }
    __syncthreads();
    float ts = 0, tq = 0;
#pragma unroll
    for (int i = 0; i < 8; i++) { ts += reds[i]; tq += redq[i]; }
    float mean = ts * (1.0f / ND);
    float var = tq * (1.0f / ND) - mean * mean;
    float rsv = rsqrtf(var + 1e-5f);
    out[(size_t)row * ND + tid] = (x0 - mean) * rsv;
    out[(size_t)row * ND + tid + 256] = (x1 - mean) * rsv;
}

// ---------------------------------------------------------------------------
extern "C" void kernel_launch(void* const* d_in, const int* in_sizes, int n_in,
                              void* d_out, int out_size)
{
    const float* query = (const float*)d_in[0];
    const float* key   = (const float*)d_in[1];
    const float* value = (const float*)d_in[2];
    const void*  amask = d_in[3];
    const void*  smask = d_in[4];
    const float* Wq = (const float*)d_in[5];
    const float* Wk = (const float*)d_in[6];
    const float* Wv = (const float*)d_in[7];
    const float* Wo = (const float*)d_in[8];

    float* out = (float*)d_out;
    float* att = ((size_t)out_size >= ACT_ELEMS + ATT_ELEMS) ? out + ACT_ELEMS : (float*)0;

    void *pQAh,*pQAl,*pKAh,*pKAl,*pVAh,*pVAl;
    void *pWQh,*pWQl,*pWKh,*pWKl,*pWVh,*pWVl,*pWOh,*pWOl;
    void *pQf,*pKf,*pVth,*pVtl,*pCh,*pCl,*pPf,*pAm,*pSm;
    cudaGetSymbolAddress(&pQAh, g_QAh); cudaGetSymbolAddress(&pQAl, g_QAl);
    cudaGetSymbolAddress(&pKAh, g_KAh); cudaGetSymbolAddress(&pKAl, g_KAl);
    cudaGetSymbolAddress(&pVAh, g_VAh); cudaGetSymbolAddress(&pVAl, g_VAl);
    cudaGetSymbolAddress(&pWQh, g_WQh); cudaGetSymbolAddress(&pWQl, g_WQl);
    cudaGetSymbolAddress(&pWKh, g_WKh); cudaGetSymbolAddress(&pWKl, g_WKl);
    cudaGetSymbolAddress(&pWVh, g_WVh); cudaGetSymbolAddress(&pWVl, g_WVl);
    cudaGetSymbolAddress(&pWOh, g_WOh); cudaGetSymbolAddress(&pWOl, g_WOl);
    cudaGetSymbolAddress(&pQf, g_Qf);   cudaGetSymbolAddress(&pKf, g_Kf);
    cudaGetSymbolAddress(&pVth, g_Vth); cudaGetSymbolAddress(&pVtl, g_Vtl);
    cudaGetSymbolAddress(&pCh, g_Ch);   cudaGetSymbolAddress(&pCl, g_Cl);
    cudaGetSymbolAddress(&pPf, g_projf);
    cudaGetSymbolAddress(&pAm, g_am);   cudaGetSymbolAddress(&pSm, g_sm);

    cudaFuncSetAttribute(proj_kernel, cudaFuncAttributeMaxDynamicSharedMemorySize, PJ_SMEM);
    cudaFuncSetAttribute(attn_kernel, cudaFuncAttributeMaxDynamicSharedMemorySize, AT_SMEM);

    cudaStream_t s1, s2, s3;
    cudaEvent_t evA, evB, evK, evV;
    cudaStreamCreateWithFlags(&s1, cudaStreamNonBlocking);
    cudaStreamCreateWithFlags(&s2, cudaStreamNonBlocking);
    cudaStreamCreateWithFlags(&s3, cudaStreamNonBlocking);
    cudaEventCreateWithFlags(&evA, cudaEventDisableTiming);
    cudaEventCreateWithFlags(&evB, cudaEventDisableTiming);
    cudaEventCreateWithFlags(&evK, cudaEventDisableTiming);
    cudaEventCreateWithFlags(&evV, cudaEventDisableTiming);

    const int nA4 = (int)(ACT_ELEMS / 4), nW4 = (int)(W_ELEMS / 4);
    dim3 pgrid(TOK / 128, ND / 128);

    detect_mask_kernel<<<1, 256>>>((const unsigned*)amask);
    cudaEventRecord(evA, 0);

    // s1: masks + Wo conversion
    cudaStreamWaitEvent(s1, evA, 0);
    pack_mask_kernel<<<MASK_WORDS / 256, 256, 0, s1>>>(amask, (unsigned*)pAm);
    pack_mask_kernel<<<MASK_WORDS / 256, 256, 0, s1>>>(smask, (unsigned*)pSm);
    conv_split_kernel<<<nW4 / 256, 256, 0, s1>>>((const float4*)Wo,
        (__nv_bfloat16*)pWOh, (__nv_bfloat16*)pWOl, nW4);
    cudaEventRecord(evB, s1);

    // s2: K pipeline
    cudaStreamWaitEvent(s2, evA, 0);
    conv_split_kernel<<<nA4 / 256, 256, 0, s2>>>((const float4*)key,
        (__nv_bfloat16*)pKAh, (__nv_bfloat16*)pKAl, nA4);
    conv_split_kernel<<<nW4 / 256, 256, 0, s2>>>((const float4*)Wk,
        (__nv_bfloat16*)pWKh, (__nv_bfloat16*)pWKl, nW4);
    proj_kernel<<<pgrid, 256, PJ_SMEM, s2>>>((const __nv_bfloat16*)pKAh, (const __nv_bfloat16*)pKAl,
        (const __nv_bfloat16*)pWKh, (const __nv_bfloat16*)pWKl,
        (float*)0, (__half*)pKf, (__half*)0, 0);
    cudaEventRecord(evK, s2);

    // s3: V pipeline
    cudaStreamWaitEvent(s3, evA, 0);
    conv_split_kernel<<<nA4 / 256, 256, 0, s3>>>((const float4*)value,
        (__nv_bfloat16*)pVAh, (__nv_bfloat16*)pVAl, nA4);
    conv_split_kernel<<<nW4 / 256, 256, 0, s3>>>((const float4*)Wv,
        (__nv_bfloat16*)pWVh, (__nv_bfloat16*)pWVl, nW4);
    proj_kernel<<<pgrid, 256, PJ_SMEM, s3>>>((const __nv_bfloat16*)pVAh, (const __nv_bfloat16*)pVAl,
        (const __nv_bfloat16*)pWVh, (const __nv_bfloat16*)pWVl,
        (float*)0, (__half*)pVth, (__half*)pVtl, 1);
    cudaEventRecord(evV, s3);

    // main: Q pipeline
    conv_split_kernel<<<nA4 / 256, 256>>>((const float4*)query,
        (__nv_bfloat16*)pQAh, (__nv_bfloat16*)pQAl, nA4);
    conv_split_kernel<<<nW4 / 256, 256>>>((const float4*)Wq,
        (__nv_bfloat16*)pWQh, (__nv_bfloat16*)pWQl, nW4);
    proj_kernel<<<pgrid, 256, PJ_SMEM>>>((const __nv_bfloat16*)pQAh, (const __nv_bfloat16*)pQAl,
        (const __nv_bfloat16*)pWQh, (const __nv_bfloat16*)pWQl,
        (float*)0, (__half*)pQf, (__half*)0, 0);

    cudaStreamWaitEvent(0, evB, 0);
    cudaStreamWaitEvent(0, evK, 0);
    cudaStreamWaitEvent(0, evV, 0);
    attn_kernel<<<dim3(NB * NH, NL / 128), 256, AT_SMEM>>>(att);

    proj_kernel<<<pgrid, 256, PJ_SMEM>>>((const __nv_bfloat16*)pCh, (const __nv_bfloat16*)pCl,
        (const __nv_bfloat16*)pWOh, (const __nv_bfloat16*)pWOl,
        (float*)pPf, (__half*)0, (__half*)0, 2);
    ln_kernel<<<TOK, 256>>>((const float*)pPf, query, out);

    cudaEventDestroy(evA); cudaEventDestroy(evB);
    cudaEventDestroy(evK); cudaEventDestroy(evV);
    cudaStreamDestroy(s1); cudaStreamDestroy(s2); cudaStreamDestroy(s3);
}

// round 15
// speedup vs baseline: 1.0361x; 1.0086x over previous
#include <cuda_runtime.h>
#include <cuda_bf16.h>
#include <cuda_fp16.h>
#include <math.h>
#include <stdint.h>

#define NB 8
#define NL 1024
#define ND 512
#define NH 8
#define NDH 64
#define TOK (NB * NL)
#define ACT_ELEMS ((size_t)TOK * ND)
#define W_ELEMS ((size_t)ND * ND)
#define ATT_ELEMS ((size_t)NB * NH * NL * NL)
#define MASK_WORDS (ATT_ELEMS / 32)

typedef unsigned long long ull;

// per-path staging buffers (no false deps between Q/K/V pipelines)
__device__ __nv_bfloat16 g_QAh[ACT_ELEMS], g_QAl[ACT_ELEMS];
__device__ __nv_bfloat16 g_KAh[ACT_ELEMS], g_KAl[ACT_ELEMS];
__device__ __nv_bfloat16 g_VAh[ACT_ELEMS], g_VAl[ACT_ELEMS];
__device__ __nv_bfloat16 g_WQh[W_ELEMS], g_WQl[W_ELEMS];
__device__ __nv_bfloat16 g_WKh[W_ELEMS], g_WKl[W_ELEMS];
__device__ __nv_bfloat16 g_WVh[W_ELEMS], g_WVl[W_ELEMS];
__device__ __nv_bfloat16 g_WOh[W_ELEMS], g_WOl[W_ELEMS];
__device__ __half       g_Qf[ACT_ELEMS], g_Kf[ACT_ELEMS];     // Q pre-scaled f16
__device__ __half       g_Vth[ACT_ELEMS], g_Vtl[ACT_ELEMS];   // [bh*64+d][1024] f16 hi/lo
__device__ __nv_bfloat16 g_Ch[ACT_ELEMS], g_Cl[ACT_ELEMS];
__device__ float        g_projf[ACT_ELEMS];
__device__ unsigned     g_am[MASK_WORDS], g_sm[MASK_WORDS];
__device__ int          g_mask_mode;

// ---------------- helpers ----------------
__device__ __forceinline__ uint32_t smem_u32(const void* p) {
    uint32_t a;
    asm("{ .reg .u64 t; cvta.to.shared.u64 t, %1; cvt.u32.u64 %0, t; }" : "=r"(a) : "l"(p));
    return a;
}
__device__ __forceinline__ void ldm_x4(unsigned r[4], uint32_t a) {
    asm volatile("ldmatrix.sync.aligned.m8n8.x4.shared.b16 {%0,%1,%2,%3}, [%4];"
                 : "=r"(r[0]), "=r"(r[1]), "=r"(r[2]), "=r"(r[3]) : "r"(a) : "memory");
}
#define MMA(c, a, b) \
    asm volatile("mma.sync.aligned.m16n8k16.row.col.f32.bf16.bf16.f32 " \
                 "{%0,%1,%2,%3},{%4,%5,%6,%7},{%8,%9},{%0,%1,%2,%3};" \
                 : "+f"((c)[0]), "+f"((c)[1]), "+f"((c)[2]), "+f"((c)[3]) \
                 : "r"((a)[0]), "r"((a)[1]), "r"((a)[2]), "r"((a)[3]), \
                   "r"((b)[0]), "r"((b)[1]))
#define MMAH(c, a, b) \
    asm volatile("mma.sync.aligned.m16n8k16.row.col.f32.f16.f16.f32 " \
                 "{%0,%1,%2,%3},{%4,%5,%6,%7},{%8,%9},{%0,%1,%2,%3};" \
                 : "+f"((c)[0]), "+f"((c)[1]), "+f"((c)[2]), "+f"((c)[3]) \
                 : "r"((a)[0]), "r"((a)[1]), "r"((a)[2]), "r"((a)[3]), \
                   "r"((b)[0]), "r"((b)[1]))

#define CP16(dst, src) \
    asm volatile("cp.async.cg.shared.global [%0], [%1], 16;" :: "r"(dst), "l"(src) : "memory")
#define CP_COMMIT() asm volatile("cp.async.commit_group;" ::: "memory")
#define CP_WAIT(n)  asm volatile("cp.async.wait_group %0;" :: "n"(n) : "memory")

// f32x2 packed ops (issue-count halvers)
__device__ __forceinline__ ull pack2(float lo, float hi) {
    ull r; asm("mov.b64 %0,{%1,%2};" : "=l"(r) : "f"(lo), "f"(hi)); return r;
}
__device__ __forceinline__ void unpack2(ull v, float& lo, float& hi) {
    asm("mov.b64 {%0,%1},%2;" : "=f"(lo), "=f"(hi) : "l"(v));
}
__device__ __forceinline__ ull ffma2(ull a, ull b, ull c) {
    ull d; asm("fma.rn.f32x2 %0,%1,%2,%3;" : "=l"(d) : "l"(a), "l"(b), "l"(c));
    return d;
}
__device__ __forceinline__ ull add2(ull a, ull b) {
    ull d; asm("add.rn.f32x2 %0,%1,%2;" : "=l"(d) : "l"(a), "l"(b));
    return d;
}
__device__ __forceinline__ ull sub2(ull a, ull b) {
    ull d; asm("sub.rn.f32x2 %0,%1,%2;" : "=l"(d) : "l"(a), "l"(b));
    return d;
}

__device__ __forceinline__ void split2(float f0, float f1, unsigned& hp, unsigned& lp) {
    __nv_bfloat16 h0 = __float2bfloat16_rn(f0), h1 = __float2bfloat16_rn(f1);
    __nv_bfloat16 l0 = __float2bfloat16_rn(f0 - __bfloat162float(h0));
    __nv_bfloat16 l1 = __float2bfloat16_rn(f1 - __bfloat162float(h1));
    hp = (unsigned)__bfloat16_as_ushort(h0) | ((unsigned)__bfloat16_as_ushort(h1) << 16);
    lp = (unsigned)__bfloat16_as_ushort(l0) | ((unsigned)__bfloat16_as_ushort(l1) << 16);
}
__device__ __forceinline__ unsigned packh2(float f0, float f1) {
    __half2 h = __floats2half2_rn(f0, f1);
    return *(unsigned*)&h;
}

// packed exp2 pair, NO clamp (caller guarantees -126 < t < 30)
// deg-4 poly, fp32 throughout, rel err ~3e-6
#define EC4 0x3C5E1D6F3C5E1D6Full  // 1.35557472e-2 packed
#define EC3 0x3D551C733D551C73ull  // 5.20323690e-2
#define EC2 0x3E7724DF3E7724DFull  // 2.41379774e-1
#define EC1 0x3F315F4B3F315F4Bull  // 6.93018210e-1
#define EC0 0x3F8000203F800020ull  // 1.00000370
__device__ __forceinline__ void fexp2x2(float t0, float t1, float& r0, float& r1) {
    int i0 = __float2int_rd(t0), i1 = __float2int_rd(t1);
    ull f = sub2(pack2(t0, t1), pack2(__int2float_rn(i0), __int2float_rn(i1)));
    ull p = ffma2(EC4, f, EC3);
    p = ffma2(p, f, EC2);
    p = ffma2(p, f, EC1);
    p = ffma2(p, f, EC0);
    float p0, p1;
    unpack2(p, p0, p1);
    r0 = __int_as_float(__float_as_int(p0) + (i0 << 23));
    r1 = __int_as_float(__float_as_int(p1) + (i1 << 23));
}

// ---------------- prep kernels ----------------
__global__ void detect_mask_kernel(const unsigned* __restrict__ m) {
    __shared__ int f32flag, u8flag;
    if (threadIdx.x == 0) { f32flag = 0; u8flag = 0; }
    __syncthreads();
    int lf = 0, lu = 0;
    for (int i = threadIdx.x; i < 4096; i += blockDim.x) {
        unsigned w = m[i];
        if (w == 0x3f800000u) lf = 1;
        else if (w > 1u) lu = 1;
    }
    if (lf) atomicOr(&f32flag, 1);
    if (lu) atomicOr(&u8flag, 1);
    __syncthreads();
    if (threadIdx.x == 0) g_mask_mode = f32flag ? 2 : (u8flag ? 0 : 1);
}

__global__ void pack_mask_kernel(const void* __restrict__ m, unsigned* __restrict__ out) {
    int w = blockIdx.x * 256 + threadIdx.x;
    if (w >= (int)MASK_WORDS) return;
    int mode = g_mask_mode;
    unsigned bits = 0;
    if (mode == 0) {
        const unsigned* p = (const unsigned*)m + (size_t)w * 8;
#pragma unroll
        for (int j = 0; j < 8; j++) {
            unsigned v = __vcmpne4(p[j], 0u);
            bits |= ((((v & 0x01010101u) * 0x01020408u) >> 24) & 0xFu) << (j * 4);
        }
    } else if (mode == 1) {
        const int* p = (const int*)m + (size_t)w * 32;
#pragma unroll
        for (int j = 0; j < 32; j++) bits |= (unsigned)(p[j] != 0) << j;
    } else {
        const float* p = (const float*)m + (size_t)w * 32;
#pragma unroll
        for (int j = 0; j < 32; j++) bits |= (unsigned)(p[j] != 0.0f) << j;
    }
    out[w] = bits;
}

__global__ void conv_split_kernel(const float4* __restrict__ x,
                                  __nv_bfloat16* __restrict__ hi,
                                  __nv_bfloat16* __restrict__ lo, int n4) {
    int i = blockIdx.x * 256 + threadIdx.x;
    if (i >= n4) return;
    float4 v = x[i];
    unsigned h0, l0, h1, l1;
    split2(v.x, v.y, h0, l0);
    split2(v.z, v.w, h1, l1);
    ((uint2*)hi)[i] = make_uint2(h0, h1);
    ((uint2*)lo)[i] = make_uint2(l0, l1);
}

// ---------------- projection GEMM (mma.sync, 3-term split bf16) ------------
// mode 0: f16 single row-major out (scaled by oscale); 1: V head-transposed
// f16 hi/lo; 2: f32.
#define SPD 72
#define PJ_AH 0
#define PJ_AL 18432
#define PJ_BH 36864
#define PJ_BL 55296
#define PJ_SMEM 73728

__global__ void __launch_bounds__(256) proj_kernel(
    const __nv_bfloat16* __restrict__ Ah, const __nv_bfloat16* __restrict__ Al,
    const __nv_bfloat16* __restrict__ Bh, const __nv_bfloat16* __restrict__ Bl,
    float* __restrict__ Cf, __half* __restrict__ Oh, __half* __restrict__ Ol,
    int mode, float oscale)
{
    extern __shared__ char smem[];
    const uint32_t sb = smem_u32(smem);
    const int tid = threadIdx.x, w = tid >> 5, lane = tid & 31;
    const int gid = lane >> 2, tig = lane & 3;
    const int m0 = blockIdx.x * 128, n0 = blockIdx.y * 128;
    const int wm = (w >> 2) * 64, wn = (w & 3) * 32;
    const int rowsel = (lane & 7) + ((lane >> 4) << 3);
    const int colsel = ((lane >> 3) & 1) * 8;

    float c[4][4][4];
#pragma unroll
    for (int mt = 0; mt < 4; mt++)
#pragma unroll
        for (int nt = 0; nt < 4; nt++)
#pragma unroll
            for (int j = 0; j < 4; j++) c[mt][nt][j] = 0.0f;

    const uint32_t aAddr = sb + ((unsigned)(wm + (lane & 15)) * SPD + (lane >> 4) * 8) * 2;
    const uint32_t bAddr4 = sb + ((unsigned)(wn + rowsel) * SPD + colsel) * 2;

    for (int kc = 0; kc < 512; kc += 64) {
#pragma unroll
        for (int it = 0; it < 4; it++) {
            int idx = it * 256 + tid, row = idx >> 3, cu = idx & 7;
            *(uint4*)(smem + PJ_AH + row * 144 + cu * 16) =
                *(const uint4*)(Ah + (size_t)(m0 + row) * 512 + kc + cu * 8);
            *(uint4*)(smem + PJ_AL + row * 144 + cu * 16) =
                *(const uint4*)(Al + (size_t)(m0 + row) * 512 + kc + cu * 8);
            *(uint4*)(smem + PJ_BH + row * 144 + cu * 16) =
                *(const uint4*)(Bh + (size_t)(n0 + row) * 512 + kc + cu * 8);
            *(uint4*)(smem + PJ_BL + row * 144 + cu * 16) =
                *(const uint4*)(Bl + (size_t)(n0 + row) * 512 + kc + cu * 8);
        }
        __syncthreads();
#pragma unroll
        for (int ks = 0; ks < 4; ks++) {
            unsigned ah[4][4], al[4][4], bh4[2][4], bl4[2][4];
#pragma unroll
            for (int mt = 0; mt < 4; mt++) {
                ldm_x4(ah[mt], aAddr + PJ_AH + (mt * 16 * SPD + ks * 16) * 2);
                ldm_x4(al[mt], aAddr + PJ_AL + (mt * 16 * SPD + ks * 16) * 2);
            }
#pragma unroll
            for (int p = 0; p < 2; p++) {
                ldm_x4(bh4[p], bAddr4 + PJ_BH + (p * 16 * SPD + ks * 16) * 2);
                ldm_x4(bl4[p], bAddr4 + PJ_BL + (p * 16 * SPD + ks * 16) * 2);
            }
#pragma unroll
            for (int mt = 0; mt < 4; mt++)
#pragma unroll
                for (int nt = 0; nt < 4; nt++) {
                    unsigned* bh = &bh4[nt >> 1][(nt & 1) * 2];
                    unsigned* bl = &bl4[nt >> 1][(nt & 1) * 2];
                    MMA(c[mt][nt], ah[mt], bh);
                    MMA(c[mt][nt], ah[mt], bl);
                    MMA(c[mt][nt], al[mt], bh);
                }
        }
        __syncthreads();
    }

    if (mode == 1) {
        float* stage = (float*)smem;  // 128 x 129 f32
#pragma unroll
        for (int mt = 0; mt < 4; mt++)
#pragma unroll
            for (int nt = 0; nt < 4; nt++) {
                int r0 = wm + mt * 16 + gid, cc0 = wn + nt * 8 + 2 * tig;
                stage[r0 * 129 + cc0] = c[mt][nt][0];
                stage[r0 * 129 + cc0 + 1] = c[mt][nt][1];
                stage[(r0 + 8) * 129 + cc0] = c[mt][nt][2];
                stage[(r0 + 8) * 129 + cc0 + 1] = c[mt][nt][3];
            }
        __syncthreads();
        const int bb = m0 >> 10, seq0 = m0 & 1023;
        const int m_local = tid & 127, nsel = tid >> 7;
#pragma unroll 8
        for (int rep = 0; rep < 64; rep++) {
            int n_local = rep * 2 + nsel;
            int n = n0 + n_local;
            int hh = n >> 6, dh = n & 63;
            size_t ob = ((size_t)((bb * 8 + hh) * 64 + dh)) * 1024 + seq0 + m_local;
            float f = stage[m_local * 129 + n_local];
            __half hv = __float2half_rn(f);
            Oh[ob] = hv;
            Ol[ob] = __float2half_rn(f - __half2float(hv));
        }
    } else if (mode == 2) {
#pragma unroll
        for (int mt = 0; mt < 4; mt++)
#pragma unroll
            for (int nt = 0; nt < 4; nt++) {
                int r0 = m0 + wm + mt * 16 + gid, cc0 = n0 + wn + nt * 8 + 2 * tig;
                *(float2*)(Cf + (size_t)r0 * 512 + cc0) =
                    make_float2(c[mt][nt][0], c[mt][nt][1]);
                *(float2*)(Cf + (size_t)(r0 + 8) * 512 + cc0) =
                    make_float2(c[mt][nt][2], c[mt][nt][3]);
            }
    } else {
        // mode 0: single f16 row-major, scaled
#pragma unroll
        for (int mt = 0; mt < 4; mt++)
#pragma unroll
            for (int nt = 0; nt < 4; nt++) {
                int r0 = m0 + wm + mt * 16 + gid, cc0 = n0 + wn + nt * 8 + 2 * tig;
                __half2 p0 = __floats2half2_rn(c[mt][nt][0] * oscale, c[mt][nt][1] * oscale);
                __half2 p1 = __floats2half2_rn(c[mt][nt][2] * oscale, c[mt][nt][3] * oscale);
                *(__half2*)(Oh + (size_t)r0 * 512 + cc0) = p0;
                *(__half2*)(Oh + (size_t)(r0 + 8) * 512 + cc0) = p1;
            }
    }
}

// ---------------- fused single-pass attention ----------------
// Q pre-scaled by 0.125*log2e; f16 single-term QK; PV 2-term; packed softmax.
// smem: sums 1024 | Q f16 18432 | 2 x (K 9216 + VH 9216 + VL 9216)
#define AT_Q 1024
#define AT_BUF0 19456
#define AT_BUFSZ 27648
#define K_OFF 0
#define VH_OFF 9216
#define VL_OFF 18432
#define AT_SMEM 74752

__global__ void __launch_bounds__(256, 2) attn_kernel(float* __restrict__ att)
{
    extern __shared__ char smem[];
    const uint32_t sb = smem_u32(smem);
    float* sums = (float*)smem;
    const int tid = threadIdx.x, w = tid >> 5, lane = tid & 31;
    const int gid = lane >> 2, tig = lane & 3;
    const int bh = blockIdx.x, b = bh >> 3, h = bh & 7;
    const int q0 = blockIdx.y * 128;
    const int rowsel = (lane & 7) + ((lane >> 4) << 3);
    const int colsel = ((lane >> 3) & 1) * 8;
    const unsigned klane = ((unsigned)rowsel * SPD + colsel) * 2;

    {
        const size_t qoff = ((size_t)(b * 1024 + q0)) * 512 + h * 64;
#pragma unroll
        for (int it = 0; it < 4; it++) {
            int idx = it * 256 + tid, row = idx >> 3, cu = idx & 7;
            *(uint4*)(smem + AT_Q + row * 144 + cu * 16) =
                *(const uint4*)(g_Qf + qoff + (size_t)row * 512 + cu * 8);
        }
    }
    __syncthreads();
    unsigned aq[4][4];
    {
        const uint32_t qa = sb + AT_Q + ((unsigned)(w * 16 + (lane & 15)) * SPD + (lane >> 4) * 8) * 2;
#pragma unroll
        for (int ks = 0; ks < 4; ks++) ldm_x4(aq[ks], qa + ks * 32);
    }
    __syncthreads();

    const size_t rb0 = (size_t)(b * 1024 + q0 + w * 16 + gid) * 32;
    const size_t rb1 = rb0 + 8 * 32;
    const size_t vbase = (size_t)(bh * 64) * 1024;
    const size_t kbase = (size_t)(b * 1024) * 512 + h * 64;

    ull rsp0 = 0ull, rsp1 = 0ull;   // packed f32x2 row-sum accumulators
    float ctx[8][4];
#pragma unroll
    for (int dt = 0; dt < 8; dt++)
#pragma unroll
        for (int j = 0; j < 4; j++) ctx[dt][j] = 0.0f;

    float* arow0 = att ? att + ((size_t)(bh * 1024 + q0 + w * 16 + gid)) * 1024 : (float*)0;
    float* arow1 = arow0 ? arow0 + (size_t)8 * 1024 : (float*)0;

    // prologue: chunk 0
    {
        const uint32_t kb = sb + AT_BUF0;
#pragma unroll
        for (int it = 0; it < 2; it++) {
            int idx = it * 256 + tid, row = idx >> 3, cu = idx & 7;
            CP16(kb + K_OFF + row * 144 + cu * 16, g_Kf + kbase + (size_t)row * 512 + cu * 8);
            CP16(kb + VH_OFF + row * 144 + cu * 16, g_Vth + vbase + (size_t)row * 1024 + cu * 8);
            CP16(kb + VL_OFF + row * 144 + cu * 16, g_Vtl + vbase + (size_t)row * 1024 + cu * 8);
        }
        CP_COMMIT();
    }

    for (int c = 0; c < 16; c++) {
        const int kc = c * 64;
        if (c < 15) {
            const uint32_t kb = sb + AT_BUF0 + ((c + 1) & 1) * AT_BUFSZ;
            const size_t koff = kbase + (size_t)(kc + 64) * 512;
#pragma unroll
            for (int it = 0; it < 2; it++) {
                int idx = it * 256 + tid, row = idx >> 3, cu = idx & 7;
                CP16(kb + K_OFF + row * 144 + cu * 16, g_Kf + koff + (size_t)row * 512 + cu * 8);
                CP16(kb + VH_OFF + row * 144 + cu * 16,
                     g_Vth + vbase + (size_t)row * 1024 + kc + 64 + cu * 8);
                CP16(kb + VL_OFF + row * 144 + cu * 16,
                     g_Vtl + vbase + (size_t)row * 1024 + kc + 64 + cu * 8);
            }
            CP_COMMIT();
            CP_WAIT(1);
        } else {
            CP_WAIT(0);
        }
        __syncthreads();

        const uint32_t bb = sb + AT_BUF0 + (c & 1) * AT_BUFSZ;
        unsigned aw0[2], aw1[2], sw0[2], sw1[2];
#pragma unroll
        for (int j = 0; j < 2; j++) {
            aw0[j] = g_am[rb0 + (kc >> 5) + j];
            aw1[j] = g_am[rb1 + (kc >> 5) + j];
            sw0[j] = g_sm[rb0 + (kc >> 5) + j];
            sw1[j] = g_sm[rb1 + (kc >> 5) + j];
        }
#pragma unroll
        for (int nt2 = 0; nt2 < 4; nt2++) {
            float cc[2][4];
#pragma unroll
            for (int hh2 = 0; hh2 < 2; hh2++)
#pragma unroll
                for (int j = 0; j < 4; j++) cc[hh2][j] = 0.0f;
#pragma unroll
            for (int ks = 0; ks < 4; ks++) {
                unsigned kh4[4];
                ldm_x4(kh4, bb + K_OFF + klane + (nt2 * 16 * SPD + ks * 16) * 2);
                MMAH(cc[0], aq[ks], &kh4[0]);
                MMAH(cc[1], aq[ks], &kh4[2]);
            }
            unsigned ph[4];
#pragma unroll
            for (int half = 0; half < 2; half++) {
                int nt = nt2 * 2 + half;
                int bidx = nt * 8 + 2 * tig;
                unsigned w0 = aw0[bidx >> 5], w1 = aw1[bidx >> 5];
                unsigned s0 = sw0[bidx >> 5], s1 = sw1[bidx >> 5];
                int bo = bidx & 31;
                // Q pre-scaled: cc IS the exp2 argument
                float t0 = cc[half][0], t1 = cc[half][1];
                float t2 = cc[half][2], t3 = cc[half][3];
                if ((w0 >> bo) & 1u) t0 = -100.0f;
                if ((w0 >> (bo + 1)) & 1u) t1 = -100.0f;
                if ((w1 >> bo) & 1u) t2 = -100.0f;
                if ((w1 >> (bo + 1)) & 1u) t3 = -100.0f;
                float p0, p1, p2, p3;
                fexp2x2(t0, t1, p0, p1);
                fexp2x2(t2, t3, p2, p3);
                rsp0 = add2(rsp0, pack2(p0, p1));
                rsp1 = add2(rsp1, pack2(p2, p3));
                if ((s0 >> bo) & 1u) p0 = 0.0f;
                if ((s0 >> (bo + 1)) & 1u) p1 = 0.0f;
                if ((s1 >> bo) & 1u) p2 = 0.0f;
                if ((s1 >> (bo + 1)) & 1u) p3 = 0.0f;
                if (arow0) {
                    *(float2*)(arow0 + kc + bidx) = make_float2(p0, p1);
                    *(float2*)(arow1 + kc + bidx) = make_float2(p2, p3);
                }
                ph[half * 2] = packh2(p0, p1);
                ph[half * 2 + 1] = packh2(p2, p3);
            }
#pragma unroll
            for (int dt2 = 0; dt2 < 4; dt2++) {
                unsigned bvh[4], bvl[4];
                ldm_x4(bvh, bb + VH_OFF + klane + (dt2 * 16 * SPD + nt2 * 16) * 2);
                ldm_x4(bvl, bb + VL_OFF + klane + (dt2 * 16 * SPD + nt2 * 16) * 2);
                MMAH(ctx[dt2 * 2], ph, &bvh[0]);
                MMAH(ctx[dt2 * 2], ph, &bvl[0]);
                MMAH(ctx[dt2 * 2 + 1], ph, &bvh[2]);
                MMAH(ctx[dt2 * 2 + 1], ph, &bvl[2]);
            }
        }
        __syncthreads();
    }

    float rs0a, rs0b, rs1a, rs1b;
    unpack2(rsp0, rs0a, rs0b);
    unpack2(rsp1, rs1a, rs1b);
    float rs0 = rs0a + rs0b, rs1 = rs1a + rs1b;
    rs0 += __shfl_xor_sync(0xffffffffu, rs0, 1);
    rs0 += __shfl_xor_sync(0xffffffffu, rs0, 2);
    rs1 += __shfl_xor_sync(0xffffffffu, rs1, 1);
    rs1 += __shfl_xor_sync(0xffffffffu, rs1, 2);
    if (tig == 0) {
        sums[w * 16 + gid] = rs0;
        sums[w * 16 + gid + 8] = rs1;
    }
    __syncthreads();
    if (tid < 128) sums[tid] = 1.0f / sums[tid];
    __syncthreads();
    const float inv0 = sums[w * 16 + gid];
    const float inv1 = sums[w * 16 + gid + 8];

    // ctx epilogue (normalized, bf16 hi/lo for Wo projection)
    {
        size_t r0 = (size_t)(b * 1024 + q0 + w * 16 + gid) * 512 + h * 64;
        size_t r1 = r0 + (size_t)8 * 512;
#pragma unroll
        for (int dt = 0; dt < 8; dt++) {
            int cc0 = dt * 8 + 2 * tig;
            unsigned hp, lp;
            split2(ctx[dt][0] * inv0, ctx[dt][1] * inv0, hp, lp);
            *(unsigned*)(g_Ch + r0 + cc0) = hp;
            *(unsigned*)(g_Cl + r0 + cc0) = lp;
            split2(ctx[dt][2] * inv1, ctx[dt][3] * inv1, hp, lp);
            *(unsigned*)(g_Ch + r1 + cc0) = hp;
            *(unsigned*)(g_Cl + r1 + cc0) = lp;
        }
    }

    // self-normalize this CTA's att rows
    if (att) {
        float4* ab = (float4*)(att + ((size_t)(bh * 1024 + q0)) * 1024);
#pragma unroll 4
        for (int i = tid; i < 128 * 256; i += 256) {
            float s = sums[i >> 8];
            float4 v = ab[i];
            v.x *= s; v.y *= s; v.z *= s; v.w *= s;
            ab[i] = v;
        }
    }
}

// ---------------- residual + LayerNorm ----------------
__global__ void __launch_bounds__(256) ln_kernel(
    const float* __restrict__ proj, const float* __restrict__ res,
    float* __restrict__ out)
{
    __shared__ float reds[8], redq[8];
    const int row = blockIdx.x, tid = threadIdx.x;
    const float* p = proj + (size_t)row * ND;
    const float* rr = res + (size_t)row * ND;
    float x0 = rr[tid] + p[tid];
    float x1 = rr[tid + 256] + p[tid + 256];
    float s = x0 + x1, q = x0 * x0 + x1 * x1;
#pragma unroll
    for (int o = 16; o > 0; o >>= 1) {
        s += __shfl_xor_sync(0xffffffffu, s, o);
        q += __shfl_xor_sync(0xffffffffu, q, o);
    }
    if ((tid & 31) == 0) { reds[tid >> 5] = s; redq[tid >> 5] = q; }
    __syncthreads();
    float ts = 0, tq = 0;
#pragma unroll
    for (int i = 0; i < 8; i++) { ts += reds[i]; tq += redq[i]; }
    float mean = ts * (1.0f / ND);
    float var = tq * (1.0f / ND) - mean * mean;
    float rsv = rsqrtf(var + 1e-5f);
    out[(size_t)row * ND + tid] = (x0 - mean) * rsv;
    out[(size_t)row * ND + tid + 256] = (x1 - mean) * rsv;
}

// ---------------------------------------------------------------------------
extern "C" void kernel_launch(void* const* d_in, const int* in_sizes, int n_in,
                              void* d_out, int out_size)
{
    const float* query = (const float*)d_in[0];
    const float* key   = (const float*)d_in[1];
    const float* value = (const float*)d_in[2];
    const void*  amask = d_in[3];
    const void*  smask = d_in[4];
    const float* Wq = (const float*)d_in[5];
    const float* Wk = (const float*)d_in[6];
    const float* Wv = (const float*)d_in[7];
    const float* Wo = (const float*)d_in[8];

    float* out = (float*)d_out;
    float* att = ((size_t)out_size >= ACT_ELEMS + ATT_ELEMS) ? out + ACT_ELEMS : (float*)0;

    void *pQAh,*pQAl,*pKAh,*pKAl,*pVAh,*pVAl;
    void *pWQh,*pWQl,*pWKh,*pWKl,*pWVh,*pWVl,*pWOh,*pWOl;
    void *pQf,*pKf,*pVth,*pVtl,*pCh,*pCl,*pPf,*pAm,*pSm;
    cudaGetSymbolAddress(&pQAh, g_QAh); cudaGetSymbolAddress(&pQAl, g_QAl);
    cudaGetSymbolAddress(&pKAh, g_KAh); cudaGetSymbolAddress(&pKAl, g_KAl);
    cudaGetSymbolAddress(&pVAh, g_VAh); cudaGetSymbolAddress(&pVAl, g_VAl);
    cudaGetSymbolAddress(&pWQh, g_WQh); cudaGetSymbolAddress(&pWQl, g_WQl);
    cudaGetSymbolAddress(&pWKh, g_WKh); cudaGetSymbolAddress(&pWKl, g_WKl);
    cudaGetSymbolAddress(&pWVh, g_WVh); cudaGetSymbolAddress(&pWVl, g_WVl);
    cudaGetSymbolAddress(&pWOh, g_WOh); cudaGetSymbolAddress(&pWOl, g_WOl);
    cudaGetSymbolAddress(&pQf, g_Qf);   cudaGetSymbolAddress(&pKf, g_Kf);
    cudaGetSymbolAddress(&pVth, g_Vth); cudaGetSymbolAddress(&pVtl, g_Vtl);
    cudaGetSymbolAddress(&pCh, g_Ch);   cudaGetSymbolAddress(&pCl, g_Cl);
    cudaGetSymbolAddress(&pPf, g_projf);
    cudaGetSymbolAddress(&pAm, g_am);   cudaGetSymbolAddress(&pSm, g_sm);

    cudaFuncSetAttribute(proj_kernel, cudaFuncAttributeMaxDynamicSharedMemorySize, PJ_SMEM);
    cudaFuncSetAttribute(attn_kernel, cudaFuncAttributeMaxDynamicSharedMemorySize, AT_SMEM);

    cudaStream_t s1, s2, s3;
    cudaEvent_t evA, evB, evK, evV;
    cudaStreamCreateWithFlags(&s1, cudaStreamNonBlocking);
    cudaStreamCreateWithFlags(&s2, cudaStreamNonBlocking);
    cudaStreamCreateWithFlags(&s3, cudaStreamNonBlocking);
    cudaEventCreateWithFlags(&evA, cudaEventDisableTiming);
    cudaEventCreateWithFlags(&evB, cudaEventDisableTiming);
    cudaEventCreateWithFlags(&evK, cudaEventDisableTiming);
    cudaEventCreateWithFlags(&evV, cudaEventDisableTiming);

    const int nA4 = (int)(ACT_ELEMS / 4), nW4 = (int)(W_ELEMS / 4);
    dim3 pgrid(TOK / 128, ND / 128);
    const float SCL = 0.18033688011112042f;  // 0.125 * log2(e), folded into Q

    detect_mask_kernel<<<1, 256>>>((const unsigned*)amask);
    cudaEventRecord(evA, 0);

    // s1: masks + Wo conversion
    cudaStreamWaitEvent(s1, evA, 0);
    pack_mask_kernel<<<MASK_WORDS / 256, 256, 0, s1>>>(amask, (unsigned*)pAm);
    pack_mask_kernel<<<MASK_WORDS / 256, 256, 0, s1>>>(smask, (unsigned*)pSm);
    conv_split_kernel<<<nW4 / 256, 256, 0, s1>>>((const float4*)Wo,
        (__nv_bfloat16*)pWOh, (__nv_bfloat16*)pWOl, nW4);
    cudaEventRecord(evB, s1);

    // s2: K pipeline
    cudaStreamWaitEvent(s2, evA, 0);
    conv_split_kernel<<<nA4 / 256, 256, 0, s2>>>((const float4*)key,
        (__nv_bfloat16*)pKAh, (__nv_bfloat16*)pKAl, nA4);
    conv_split_kernel<<<nW4 / 256, 256, 0, s2>>>((const float4*)Wk,
        (__nv_bfloat16*)pWKh, (__nv_bfloat16*)pWKl, nW4);
    proj_kernel<<<pgrid, 256, PJ_SMEM, s2>>>((const __nv_bfloat16*)pKAh, (const __nv_bfloat16*)pKAl,
        (const __nv_bfloat16*)pWKh, (const __nv_bfloat16*)pWKl,
        (float*)0, (__half*)pKf, (__half*)0, 0, 1.0f);
    cudaEventRecord(evK, s2);

    // s3: V pipeline
    cudaStreamWaitEvent(s3, evA, 0);
    conv_split_kernel<<<nA4 / 256, 256, 0, s3>>>((const float4*)value,
        (__nv_bfloat16*)pVAh, (__nv_bfloat16*)pVAl, nA4);
    conv_split_kernel<<<nW4 / 256, 256, 0, s3>>>((const float4*)Wv,
        (__nv_bfloat16*)pWVh, (__nv_bfloat16*)pWVl, nW4);
    proj_kernel<<<pgrid, 256, PJ_SMEM, s3>>>((const __nv_bfloat16*)pVAh, (const __nv_bfloat16*)pVAl,
        (const __nv_bfloat16*)pWVh, (const __nv_bfloat16*)pWVl,
        (float*)0, (__half*)pVth, (__half*)pVtl, 1, 1.0f);
    cudaEventRecord(evV, s3);

    // main: Q pipeline (pre-scaled by SCL)
    conv_split_kernel<<<nA4 / 256, 256>>>((const float4*)query,
        (__nv_bfloat16*)pQAh, (__nv_bfloat16*)pQAl, nA4);
    conv_split_kernel<<<nW4 / 256, 256>>>((const float4*)Wq,
        (__nv_bfloat16*)pWQh, (__nv_bfloat16*)pWQl, nW4);
    proj_kernel<<<pgrid, 256, PJ_SMEM>>>((const __nv_bfloat16*)pQAh, (const __nv_bfloat16*)pQAl,
        (const __nv_bfloat16*)pWQh, (const __nv_bfloat16*)pWQl,
        (float*)0, (__half*)pQf, (__half*)0, 0, SCL);

    cudaStreamWaitEvent(0, evB, 0);
    cudaStreamWaitEvent(0, evK, 0);
    cudaStreamWaitEvent(0, evV, 0);
    attn_kernel<<<dim3(NB * NH, NL / 128), 256, AT_SMEM>>>(att);

    proj_kernel<<<pgrid, 256, PJ_SMEM>>>((const __nv_bfloat16*)pCh, (const __nv_bfloat16*)pCl,
        (const __nv_bfloat16*)pWOh, (const __nv_bfloat16*)pWOl,
        (float*)pPf, (__half*)0, (__half*)0, 2, 1.0f);
    ln_kernel<<<TOK, 256>>>((const float*)pPf, query, out);

    cudaEventDestroy(evA); cudaEventDestroy(evB);
    cudaEventDestroy(evK); cudaEventDestroy(evV);
    cudaStreamDestroy(s1); cudaStreamDestroy(s2); cudaStreamDestroy(s3);
}

// round 16
// speedup vs baseline: 1.0636x; 1.0266x over previous
#include <cuda_runtime.h>
#include <cuda_bf16.h>
#include <cuda_fp16.h>
#include <math.h>
#include <stdint.h>

#define NB 8
#define NL 1024
#define ND 512
#define NH 8
#define NDH 64
#define TOK (NB * NL)
#define ACT_ELEMS ((size_t)TOK * ND)
#define W_ELEMS ((size_t)ND * ND)
#define ATT_ELEMS ((size_t)NB * NH * NL * NL)
#define MASK_WORDS (ATT_ELEMS / 32)

typedef unsigned long long ull;

__device__ __nv_bfloat16 g_QAh[ACT_ELEMS], g_QAl[ACT_ELEMS];
__device__ __nv_bfloat16 g_KAh[ACT_ELEMS], g_KAl[ACT_ELEMS];
__device__ __nv_bfloat16 g_VAh[ACT_ELEMS], g_VAl[ACT_ELEMS];
__device__ __nv_bfloat16 g_WQh[W_ELEMS], g_WQl[W_ELEMS];
__device__ __nv_bfloat16 g_WKh[W_ELEMS], g_WKl[W_ELEMS];
__device__ __nv_bfloat16 g_WVh[W_ELEMS], g_WVl[W_ELEMS];
__device__ __nv_bfloat16 g_WOh[W_ELEMS], g_WOl[W_ELEMS];
__device__ __half       g_Qf[ACT_ELEMS], g_Kf[ACT_ELEMS];   // Q pre-scaled f16
__device__ __half       g_Vt[ACT_ELEMS];                    // [bh*64+d][1024] single f16
__device__ __nv_bfloat16 g_Ch[ACT_ELEMS], g_Cl[ACT_ELEMS];
__device__ float        g_projf[ACT_ELEMS];
__device__ unsigned     g_am[MASK_WORDS], g_sm[MASK_WORDS];
__device__ int          g_mask_mode;

// ---------------- helpers ----------------
__device__ __forceinline__ uint32_t smem_u32(const void* p) {
    uint32_t a;
    asm("{ .reg .u64 t; cvta.to.shared.u64 t, %1; cvt.u32.u64 %0, t; }" : "=r"(a) : "l"(p));
    return a;
}
__device__ __forceinline__ void ldm_x4(unsigned r[4], uint32_t a) {
    asm volatile("ldmatrix.sync.aligned.m8n8.x4.shared.b16 {%0,%1,%2,%3}, [%4];"
                 : "=r"(r[0]), "=r"(r[1]), "=r"(r[2]), "=r"(r[3]) : "r"(a) : "memory");
}
#define MMA(c, a, b) \
    asm volatile("mma.sync.aligned.m16n8k16.row.col.f32.bf16.bf16.f32 " \
                 "{%0,%1,%2,%3},{%4,%5,%6,%7},{%8,%9},{%0,%1,%2,%3};" \
                 : "+f"((c)[0]), "+f"((c)[1]), "+f"((c)[2]), "+f"((c)[3]) \
                 : "r"((a)[0]), "r"((a)[1]), "r"((a)[2]), "r"((a)[3]), \
                   "r"((b)[0]), "r"((b)[1]))
#define MMAH(c, a, b) \
    asm volatile("mma.sync.aligned.m16n8k16.row.col.f32.f16.f16.f32 " \
                 "{%0,%1,%2,%3},{%4,%5,%6,%7},{%8,%9},{%0,%1,%2,%3};" \
                 : "+f"((c)[0]), "+f"((c)[1]), "+f"((c)[2]), "+f"((c)[3]) \
                 : "r"((a)[0]), "r"((a)[1]), "r"((a)[2]), "r"((a)[3]), \
                   "r"((b)[0]), "r"((b)[1]))

#define CP16(dst, src) \
    asm volatile("cp.async.cg.shared.global [%0], [%1], 16;" :: "r"(dst), "l"(src) : "memory")
#define CP_COMMIT() asm volatile("cp.async.commit_group;" ::: "memory")
#define CP_WAIT(n)  asm volatile("cp.async.wait_group %0;" :: "n"(n) : "memory")

__device__ __forceinline__ ull pack2(float lo, float hi) {
    ull r; asm("mov.b64 %0,{%1,%2};" : "=l"(r) : "f"(lo), "f"(hi)); return r;
}
__device__ __forceinline__ void unpack2(ull v, float& lo, float& hi) {
    asm("mov.b64 {%0,%1},%2;" : "=f"(lo), "=f"(hi) : "l"(v));
}
__device__ __forceinline__ ull ffma2(ull a, ull b, ull c) {
    ull d; asm("fma.rn.f32x2 %0,%1,%2,%3;" : "=l"(d) : "l"(a), "l"(b), "l"(c));
    return d;
}
__device__ __forceinline__ ull add2(ull a, ull b) {
    ull d; asm("add.rn.f32x2 %0,%1,%2;" : "=l"(d) : "l"(a), "l"(b));
    return d;
}
__device__ __forceinline__ ull sub2(ull a, ull b) {
    ull d; asm("sub.rn.f32x2 %0,%1,%2;" : "=l"(d) : "l"(a), "l"(b));
    return d;
}

__device__ __forceinline__ void split2(float f0, float f1, unsigned& hp, unsigned& lp) {
    __nv_bfloat16 h0 = __float2bfloat16_rn(f0), h1 = __float2bfloat16_rn(f1);
    __nv_bfloat16 l0 = __float2bfloat16_rn(f0 - __bfloat162float(h0));
    __nv_bfloat16 l1 = __float2bfloat16_rn(f1 - __bfloat162float(h1));
    hp = (unsigned)__bfloat16_as_ushort(h0) | ((unsigned)__bfloat16_as_ushort(h1) << 16);
    lp = (unsigned)__bfloat16_as_ushort(l0) | ((unsigned)__bfloat16_as_ushort(l1) << 16);
}
__device__ __forceinline__ unsigned packh2(float f0, float f1) {
    __half2 h = __floats2half2_rn(f0, f1);
    return *(unsigned*)&h;
}

// packed exp2 pair, no clamp (caller guarantees -126 < t < 30)
#define EC4 0x3C5E1D6F3C5E1D6Full
#define EC3 0x3D551C733D551C73ull
#define EC2 0x3E7724DF3E7724DFull
#define EC1 0x3F315F4B3F315F4Bull
#define EC0 0x3F8000203F800020ull
__device__ __forceinline__ void fexp2x2(float t0, float t1, float& r0, float& r1) {
    int i0 = __float2int_rd(t0), i1 = __float2int_rd(t1);
    ull f = sub2(pack2(t0, t1), pack2(__int2float_rn(i0), __int2float_rn(i1)));
    ull p = ffma2(EC4, f, EC3);
    p = ffma2(p, f, EC2);
    p = ffma2(p, f, EC1);
    p = ffma2(p, f, EC0);
    float p0, p1;
    unpack2(p, p0, p1);
    r0 = __int_as_float(__float_as_int(p0) + (i0 << 23));
    r1 = __int_as_float(__float_as_int(p1) + (i1 << 23));
}

// ---------------- prep kernels ----------------
__global__ void detect_mask_kernel(const unsigned* __restrict__ m) {
    __shared__ int f32flag, u8flag;
    if (threadIdx.x == 0) { f32flag = 0; u8flag = 0; }
    __syncthreads();
    int lf = 0, lu = 0;
    for (int i = threadIdx.x; i < 4096; i += blockDim.x) {
        unsigned w = m[i];
        if (w == 0x3f800000u) lf = 1;
        else if (w > 1u) lu = 1;
    }
    if (lf) atomicOr(&f32flag, 1);
    if (lu) atomicOr(&u8flag, 1);
    __syncthreads();
    if (threadIdx.x == 0) g_mask_mode = f32flag ? 2 : (u8flag ? 0 : 1);
}

__global__ void pack_mask_kernel(const void* __restrict__ m, unsigned* __restrict__ out) {
    int w = blockIdx.x * 256 + threadIdx.x;
    if (w >= (int)MASK_WORDS) return;
    int mode = g_mask_mode;
    unsigned bits = 0;
    if (mode == 0) {
        const unsigned* p = (const unsigned*)m + (size_t)w * 8;
#pragma unroll
        for (int j = 0; j < 8; j++) {
            unsigned v = __vcmpne4(p[j], 0u);
            bits |= ((((v & 0x01010101u) * 0x01020408u) >> 24) & 0xFu) << (j * 4);
        }
    } else if (mode == 1) {
        const int* p = (const int*)m + (size_t)w * 32;
#pragma unroll
        for (int j = 0; j < 32; j++) bits |= (unsigned)(p[j] != 0) << j;
    } else {
        const float* p = (const float*)m + (size_t)w * 32;
#pragma unroll
        for (int j = 0; j < 32; j++) bits |= (unsigned)(p[j] != 0.0f) << j;
    }
    out[w] = bits;
}

__global__ void conv_split_kernel(const float4* __restrict__ x,
                                  __nv_bfloat16* __restrict__ hi,
                                  __nv_bfloat16* __restrict__ lo, int n4) {
    int i = blockIdx.x * 256 + threadIdx.x;
    if (i >= n4) return;
    float4 v = x[i];
    unsigned h0, l0, h1, l1;
    split2(v.x, v.y, h0, l0);
    split2(v.z, v.w, h1, l1);
    ((uint2*)hi)[i] = make_uint2(h0, h1);
    ((uint2*)lo)[i] = make_uint2(l0, l1);
}

// ---------------- projection GEMM (mma.sync, 3-term split bf16) ------------
// mode 0: f16 single row-major out (scaled); 1: V head-transposed single f16;
// 2: f32.
#define SPD 72
#define PJ_AH 0
#define PJ_AL 18432
#define PJ_BH 36864
#define PJ_BL 55296
#define PJ_SMEM 73728

__global__ void __launch_bounds__(256) proj_kernel(
    const __nv_bfloat16* __restrict__ Ah, const __nv_bfloat16* __restrict__ Al,
    const __nv_bfloat16* __restrict__ Bh, const __nv_bfloat16* __restrict__ Bl,
    float* __restrict__ Cf, __half* __restrict__ Oh, int mode, float oscale)
{
    extern __shared__ char smem[];
    const uint32_t sb = smem_u32(smem);
    const int tid = threadIdx.x, w = tid >> 5, lane = tid & 31;
    const int gid = lane >> 2, tig = lane & 3;
    const int m0 = blockIdx.x * 128, n0 = blockIdx.y * 128;
    const int wm = (w >> 2) * 64, wn = (w & 3) * 32;
    const int rowsel = (lane & 7) + ((lane >> 4) << 3);
    const int colsel = ((lane >> 3) & 1) * 8;

    float c[4][4][4];
#pragma unroll
    for (int mt = 0; mt < 4; mt++)
#pragma unroll
        for (int nt = 0; nt < 4; nt++)
#pragma unroll
            for (int j = 0; j < 4; j++) c[mt][nt][j] = 0.0f;

    const uint32_t aAddr = sb + ((unsigned)(wm + (lane & 15)) * SPD + (lane >> 4) * 8) * 2;
    const uint32_t bAddr4 = sb + ((unsigned)(wn + rowsel) * SPD + colsel) * 2;

    for (int kc = 0; kc < 512; kc += 64) {
#pragma unroll
        for (int it = 0; it < 4; it++) {
            int idx = it * 256 + tid, row = idx >> 3, cu = idx & 7;
            *(uint4*)(smem + PJ_AH + row * 144 + cu * 16) =
                *(const uint4*)(Ah + (size_t)(m0 + row) * 512 + kc + cu * 8);
            *(uint4*)(smem + PJ_AL + row * 144 + cu * 16) =
                *(const uint4*)(Al + (size_t)(m0 + row) * 512 + kc + cu * 8);
            *(uint4*)(smem + PJ_BH + row * 144 + cu * 16) =
                *(const uint4*)(Bh + (size_t)(n0 + row) * 512 + kc + cu * 8);
            *(uint4*)(smem + PJ_BL + row * 144 + cu * 16) =
                *(const uint4*)(Bl + (size_t)(n0 + row) * 512 + kc + cu * 8);
        }
        __syncthreads();
#pragma unroll
        for (int ks = 0; ks < 4; ks++) {
            unsigned ah[4][4], al[4][4], bh4[2][4], bl4[2][4];
#pragma unroll
            for (int mt = 0; mt < 4; mt++) {
                ldm_x4(ah[mt], aAddr + PJ_AH + (mt * 16 * SPD + ks * 16) * 2);
                ldm_x4(al[mt], aAddr + PJ_AL + (mt * 16 * SPD + ks * 16) * 2);
            }
#pragma unroll
            for (int p = 0; p < 2; p++) {
                ldm_x4(bh4[p], bAddr4 + PJ_BH + (p * 16 * SPD + ks * 16) * 2);
                ldm_x4(bl4[p], bAddr4 + PJ_BL + (p * 16 * SPD + ks * 16) * 2);
            }
#pragma unroll
            for (int mt = 0; mt < 4; mt++)
#pragma unroll
                for (int nt = 0; nt < 4; nt++) {
                    unsigned* bh = &bh4[nt >> 1][(nt & 1) * 2];
                    unsigned* bl = &bl4[nt >> 1][(nt & 1) * 2];
                    MMA(c[mt][nt], ah[mt], bh);
                    MMA(c[mt][nt], ah[mt], bl);
                    MMA(c[mt][nt], al[mt], bh);
                }
        }
        __syncthreads();
    }

    if (mode == 1) {
        float* stage = (float*)smem;  // 128 x 129 f32
#pragma unroll
        for (int mt = 0; mt < 4; mt++)
#pragma unroll
            for (int nt = 0; nt < 4; nt++) {
                int r0 = wm + mt * 16 + gid, cc0 = wn + nt * 8 + 2 * tig;
                stage[r0 * 129 + cc0] = c[mt][nt][0];
                stage[r0 * 129 + cc0 + 1] = c[mt][nt][1];
                stage[(r0 + 8) * 129 + cc0] = c[mt][nt][2];
                stage[(r0 + 8) * 129 + cc0 + 1] = c[mt][nt][3];
            }
        __syncthreads();
        const int bb = m0 >> 10, seq0 = m0 & 1023;
        const int m_local = tid & 127, nsel = tid >> 7;
#pragma unroll 8
        for (int rep = 0; rep < 64; rep++) {
            int n_local = rep * 2 + nsel;
            int n = n0 + n_local;
            int hh = n >> 6, dh = n & 63;
            size_t ob = ((size_t)((bb * 8 + hh) * 64 + dh)) * 1024 + seq0 + m_local;
            Oh[ob] = __float2half_rn(stage[m_local * 129 + n_local]);
        }
    } else if (mode == 2) {
#pragma unroll
        for (int mt = 0; mt < 4; mt++)
#pragma unroll
            for (int nt = 0; nt < 4; nt++) {
                int r0 = m0 + wm + mt * 16 + gid, cc0 = n0 + wn + nt * 8 + 2 * tig;
                *(float2*)(Cf + (size_t)r0 * 512 + cc0) =
                    make_float2(c[mt][nt][0], c[mt][nt][1]);
                *(float2*)(Cf + (size_t)(r0 + 8) * 512 + cc0) =
                    make_float2(c[mt][nt][2], c[mt][nt][3]);
            }
    } else {
#pragma unroll
        for (int mt = 0; mt < 4; mt++)
#pragma unroll
            for (int nt = 0; nt < 4; nt++) {
                int r0 = m0 + wm + mt * 16 + gid, cc0 = n0 + wn + nt * 8 + 2 * tig;
                __half2 p0 = __floats2half2_rn(c[mt][nt][0] * oscale, c[mt][nt][1] * oscale);
                __half2 p1 = __floats2half2_rn(c[mt][nt][2] * oscale, c[mt][nt][3] * oscale);
                *(__half2*)(Oh + (size_t)r0 * 512 + cc0) = p0;
                *(__half2*)(Oh + (size_t)(r0 + 8) * 512 + cc0) = p1;
            }
    }
}

// ---------------- fused single-pass attention ----------------
// Q pre-scaled; f16 single-term QK; PV single-f16 V. Packed softmax.
// smem: sums 1024 | Q f16 18432 | 2 x (K 9216 + V 9216)
#define AT_Q 1024
#define AT_BUF0 19456
#define AT_BUFSZ 18432
#define K_OFF 0
#define V_OFF 9216
#define AT_SMEM 56320

__global__ void __launch_bounds__(256, 2) attn_kernel(float* __restrict__ att)
{
    extern __shared__ char smem[];
    const uint32_t sb = smem_u32(smem);
    float* sums = (float*)smem;
    const int tid = threadIdx.x, w = tid >> 5, lane = tid & 31;
    const int gid = lane >> 2, tig = lane & 3;
    const int bh = blockIdx.x, b = bh >> 3, h = bh & 7;
    const int q0 = blockIdx.y * 128;
    const int rowsel = (lane & 7) + ((lane >> 4) << 3);
    const int colsel = ((lane >> 3) & 1) * 8;
    const unsigned klane = ((unsigned)rowsel * SPD + colsel) * 2;

    {
        const size_t qoff = ((size_t)(b * 1024 + q0)) * 512 + h * 64;
#pragma unroll
        for (int it = 0; it < 4; it++) {
            int idx = it * 256 + tid, row = idx >> 3, cu = idx & 7;
            *(uint4*)(smem + AT_Q + row * 144 + cu * 16) =
                *(const uint4*)(g_Qf + qoff + (size_t)row * 512 + cu * 8);
        }
    }
    __syncthreads();
    unsigned aq[4][4];
    {
        const uint32_t qa = sb + AT_Q + ((unsigned)(w * 16 + (lane & 15)) * SPD + (lane >> 4) * 8) * 2;
#pragma unroll
        for (int ks = 0; ks < 4; ks++) ldm_x4(aq[ks], qa + ks * 32);
    }
    __syncthreads();

    const size_t rb0 = (size_t)(b * 1024 + q0 + w * 16 + gid) * 32;
    const size_t rb1 = rb0 + 8 * 32;
    const size_t vbase = (size_t)(bh * 64) * 1024;
    const size_t kbase = (size_t)(b * 1024) * 512 + h * 64;

    ull rsp0 = 0ull, rsp1 = 0ull;
    float ctx[8][4];
#pragma unroll
    for (int dt = 0; dt < 8; dt++)
#pragma unroll
        for (int j = 0; j < 4; j++) ctx[dt][j] = 0.0f;

    float* arow0 = att ? att + ((size_t)(bh * 1024 + q0 + w * 16 + gid)) * 1024 : (float*)0;
    float* arow1 = arow0 ? arow0 + (size_t)8 * 1024 : (float*)0;

    // prologue: chunk 0
    {
        const uint32_t kb = sb + AT_BUF0;
#pragma unroll
        for (int it = 0; it < 2; it++) {
            int idx = it * 256 + tid, row = idx >> 3, cu = idx & 7;
            CP16(kb + K_OFF + row * 144 + cu * 16, g_Kf + kbase + (size_t)row * 512 + cu * 8);
            CP16(kb + V_OFF + row * 144 + cu * 16, g_Vt + vbase + (size_t)row * 1024 + cu * 8);
        }
        CP_COMMIT();
    }

    for (int c = 0; c < 16; c++) {
        const int kc = c * 64;
        if (c < 15) {
            const uint32_t kb = sb + AT_BUF0 + ((c + 1) & 1) * AT_BUFSZ;
            const size_t koff = kbase + (size_t)(kc + 64) * 512;
#pragma unroll
            for (int it = 0; it < 2; it++) {
                int idx = it * 256 + tid, row = idx >> 3, cu = idx & 7;
                CP16(kb + K_OFF + row * 144 + cu * 16, g_Kf + koff + (size_t)row * 512 + cu * 8);
                CP16(kb + V_OFF + row * 144 + cu * 16,
                     g_Vt + vbase + (size_t)row * 1024 + kc + 64 + cu * 8);
            }
            CP_COMMIT();
            CP_WAIT(1);
        } else {
            CP_WAIT(0);
        }
        __syncthreads();

        const uint32_t bb = sb + AT_BUF0 + (c & 1) * AT_BUFSZ;
        unsigned aw0[2], aw1[2], sw0[2], sw1[2];
#pragma unroll
        for (int j = 0; j < 2; j++) {
            aw0[j] = g_am[rb0 + (kc >> 5) + j];
            aw1[j] = g_am[rb1 + (kc >> 5) + j];
            sw0[j] = g_sm[rb0 + (kc >> 5) + j];
            sw1[j] = g_sm[rb1 + (kc >> 5) + j];
        }
#pragma unroll
        for (int nt2 = 0; nt2 < 4; nt2++) {
            float cc[2][4];
#pragma unroll
            for (int hh2 = 0; hh2 < 2; hh2++)
#pragma unroll
                for (int j = 0; j < 4; j++) cc[hh2][j] = 0.0f;
#pragma unroll
            for (int ks = 0; ks < 4; ks++) {
                unsigned kh4[4];
                ldm_x4(kh4, bb + K_OFF + klane + (nt2 * 16 * SPD + ks * 16) * 2);
                MMAH(cc[0], aq[ks], &kh4[0]);
                MMAH(cc[1], aq[ks], &kh4[2]);
            }
            unsigned ph[4];
#pragma unroll
            for (int half = 0; half < 2; half++) {
                int nt = nt2 * 2 + half;
                int bidx = nt * 8 + 2 * tig;
                unsigned w0 = aw0[bidx >> 5], w1 = aw1[bidx >> 5];
                unsigned s0 = sw0[bidx >> 5], s1 = sw1[bidx >> 5];
                int bo = bidx & 31;
                float t0 = cc[half][0], t1 = cc[half][1];
                float t2 = cc[half][2], t3 = cc[half][3];
                if ((w0 >> bo) & 1u) t0 = -100.0f;
                if ((w0 >> (bo + 1)) & 1u) t1 = -100.0f;
                if ((w1 >> bo) & 1u) t2 = -100.0f;
                if ((w1 >> (bo + 1)) & 1u) t3 = -100.0f;
                float p0, p1, p2, p3;
                fexp2x2(t0, t1, p0, p1);
                fexp2x2(t2, t3, p2, p3);
                rsp0 = add2(rsp0, pack2(p0, p1));
                rsp1 = add2(rsp1, pack2(p2, p3));
                if ((s0 >> bo) & 1u) p0 = 0.0f;
                if ((s0 >> (bo + 1)) & 1u) p1 = 0.0f;
                if ((s1 >> bo) & 1u) p2 = 0.0f;
                if ((s1 >> (bo + 1)) & 1u) p3 = 0.0f;
                if (arow0) {
                    *(float2*)(arow0 + kc + bidx) = make_float2(p0, p1);
                    *(float2*)(arow1 + kc + bidx) = make_float2(p2, p3);
                }
                ph[half * 2] = packh2(p0, p1);
                ph[half * 2 + 1] = packh2(p2, p3);
            }
#pragma unroll
            for (int dt2 = 0; dt2 < 4; dt2++) {
                unsigned bv[4];
                ldm_x4(bv, bb + V_OFF + klane + (dt2 * 16 * SPD + nt2 * 16) * 2);
                MMAH(ctx[dt2 * 2], ph, &bv[0]);
                MMAH(ctx[dt2 * 2 + 1], ph, &bv[2]);
            }
        }
        __syncthreads();
    }

    float rs0a, rs0b, rs1a, rs1b;
    unpack2(rsp0, rs0a, rs0b);
    unpack2(rsp1, rs1a, rs1b);
    float rs0 = rs0a + rs0b, rs1 = rs1a + rs1b;
    rs0 += __shfl_xor_sync(0xffffffffu, rs0, 1);
    rs0 += __shfl_xor_sync(0xffffffffu, rs0, 2);
    rs1 += __shfl_xor_sync(0xffffffffu, rs1, 1);
    rs1 += __shfl_xor_sync(0xffffffffu, rs1, 2);
    if (tig == 0) {
        sums[w * 16 + gid] = rs0;
        sums[w * 16 + gid + 8] = rs1;
    }
    __syncthreads();
    if (tid < 128) sums[tid] = 1.0f / sums[tid];
    __syncthreads();
    const float inv0 = sums[w * 16 + gid];
    const float inv1 = sums[w * 16 + gid + 8];

    // ctx epilogue (normalized, bf16 hi/lo for Wo projection)
    {
        size_t r0 = (size_t)(b * 1024 + q0 + w * 16 + gid) * 512 + h * 64;
        size_t r1 = r0 + (size_t)8 * 512;
#pragma unroll
        for (int dt = 0; dt < 8; dt++) {
            int cc0 = dt * 8 + 2 * tig;
            unsigned hp, lp;
            split2(ctx[dt][0] * inv0, ctx[dt][1] * inv0, hp, lp);
            *(unsigned*)(g_Ch + r0 + cc0) = hp;
            *(unsigned*)(g_Cl + r0 + cc0) = lp;
            split2(ctx[dt][2] * inv1, ctx[dt][3] * inv1, hp, lp);
            *(unsigned*)(g_Ch + r1 + cc0) = hp;
            *(unsigned*)(g_Cl + r1 + cc0) = lp;
        }
    }

    // self-normalize this CTA's att rows
    if (att) {
        float4* ab = (float4*)(att + ((size_t)(bh * 1024 + q0)) * 1024);
#pragma unroll 4
        for (int i = tid; i < 128 * 256; i += 256) {
            float s = sums[i >> 8];
            float4 v = ab[i];
            v.x *= s; v.y *= s; v.z *= s; v.w *= s;
            ab[i] = v;
        }
    }
}

// ---------------- residual + LayerNorm ----------------
__global__ void __launch_bounds__(256) ln_kernel(
    const float* __restrict__ proj, const float* __restrict__ res,
    float* __restrict__ out)
{
    __shared__ float reds[8], redq[8];
    const int row = blockIdx.x, tid = threadIdx.x;
    const float* p = proj + (size_t)row * ND;
    const float* rr = res + (size_t)row * ND;
    float x0 = rr[tid] + p[tid];
    float x1 = rr[tid + 256] + p[tid + 256];
    float s = x0 + x1, q = x0 * x0 + x1 * x1;
#pragma unroll
    for (int o = 16; o > 0; o >>= 1) {
        s += __shfl_xor_sync(0xffffffffu, s, o);
        q += __shfl_xor_sync(0xffffffffu, q, o);
    }
    if ((tid & 31) == 0) { reds[tid >> 5] = s; redq[tid >> 5] = q; }
    __syncthreads();
    float ts = 0, tq = 0;
#pragma unroll
    for (int i = 0; i < 8; i++) { ts += reds[i]; tq += redq[i]; }
    float mean = ts * (1.0f / ND);
    float var = tq * (1.0f / ND) - mean * mean;
    float rsv = rsqrtf(var + 1e-5f);
    out[(size_t)row * ND + tid] = (x0 - mean) * rsv;
    out[(size_t)row * ND + tid + 256] = (x1 - mean) * rsv;
}

// ---------------------------------------------------------------------------
extern "C" void kernel_launch(void* const* d_in, const int* in_sizes, int n_in,
                              void* d_out, int out_size)
{
    const float* query = (const float*)d_in[0];
    const float* key   = (const float*)d_in[1];
    const float* value = (const float*)d_in[2];
    const void*  amask = d_in[3];
    const void*  smask = d_in[4];
    const float* Wq = (const float*)d_in[5];
    const float* Wk = (const float*)d_in[6];
    const float* Wv = (const float*)d_in[7];
    const float* Wo = (const float*)d_in[8];

    float* out = (float*)d_out;
    float* att = ((size_t)out_size >= ACT_ELEMS + ATT_ELEMS) ? out + ACT_ELEMS : (float*)0;

    void *pQAh,*pQAl,*pKAh,*pKAl,*pVAh,*pVAl;
    void *pWQh,*pWQl,*pWKh,*pWKl,*pWVh,*pWVl,*pWOh,*pWOl;
    void *pQf,*pKf,*pVt,*pCh,*pCl,*pPf,*pAm,*pSm;
    cudaGetSymbolAddress(&pQAh, g_QAh); cudaGetSymbolAddress(&pQAl, g_QAl);
    cudaGetSymbolAddress(&pKAh, g_KAh); cudaGetSymbolAddress(&pKAl, g_KAl);
    cudaGetSymbolAddress(&pVAh, g_VAh); cudaGetSymbolAddress(&pVAl, g_VAl);
    cudaGetSymbolAddress(&pWQh, g_WQh); cudaGetSymbolAddress(&pWQl, g_WQl);
    cudaGetSymbolAddress(&pWKh, g_WKh); cudaGetSymbolAddress(&pWKl, g_WKl);
    cudaGetSymbolAddress(&pWVh, g_WVh); cudaGetSymbolAddress(&pWVl, g_WVl);
    cudaGetSymbolAddress(&pWOh, g_WOh); cudaGetSymbolAddress(&pWOl, g_WOl);
    cudaGetSymbolAddress(&pQf, g_Qf);   cudaGetSymbolAddress(&pKf, g_Kf);
    cudaGetSymbolAddress(&pVt, g_Vt);
    cudaGetSymbolAddress(&pCh, g_Ch);   cudaGetSymbolAddress(&pCl, g_Cl);
    cudaGetSymbolAddress(&pPf, g_projf);
    cudaGetSymbolAddress(&pAm, g_am);   cudaGetSymbolAddress(&pSm, g_sm);

    cudaFuncSetAttribute(proj_kernel, cudaFuncAttributeMaxDynamicSharedMemorySize, PJ_SMEM);
    cudaFuncSetAttribute(attn_kernel, cudaFuncAttributeMaxDynamicSharedMemorySize, AT_SMEM);

    cudaStream_t s1, s2, s3;
    cudaEvent_t evA, evB, evK, evV;
    cudaStreamCreateWithFlags(&s1, cudaStreamNonBlocking);
    cudaStreamCreateWithFlags(&s2, cudaStreamNonBlocking);
    cudaStreamCreateWithFlags(&s3, cudaStreamNonBlocking);
    cudaEventCreateWithFlags(&evA, cudaEventDisableTiming);
    cudaEventCreateWithFlags(&evB, cudaEventDisableTiming);
    cudaEventCreateWithFlags(&evK, cudaEventDisableTiming);
    cudaEventCreateWithFlags(&evV, cudaEventDisableTiming);

    const int nA4 = (int)(ACT_ELEMS / 4), nW4 = (int)(W_ELEMS / 4);
    dim3 pgrid(TOK / 128, ND / 128);
    const float SCL = 0.18033688011112042f;

    detect_mask_kernel<<<1, 256>>>((const unsigned*)amask);
    cudaEventRecord(evA, 0);

    cudaStreamWaitEvent(s1, evA, 0);
    pack_mask_kernel<<<MASK_WORDS / 256, 256, 0, s1>>>(amask, (unsigned*)pAm);
    pack_mask_kernel<<<MASK_WORDS / 256, 256, 0, s1>>>(smask, (unsigned*)pSm);
    conv_split_kernel<<<nW4 / 256, 256, 0, s1>>>((const float4*)Wo,
        (__nv_bfloat16*)pWOh, (__nv_bfloat16*)pWOl, nW4);
    cudaEventRecord(evB, s1);

    cudaStreamWaitEvent(s2, evA, 0);
    conv_split_kernel<<<nA4 / 256, 256, 0, s2>>>((const float4*)key,
        (__nv_bfloat16*)pKAh, (__nv_bfloat16*)pKAl, nA4);
    conv_split_kernel<<<nW4 / 256, 256, 0, s2>>>((const float4*)Wk,
        (__nv_bfloat16*)pWKh, (__nv_bfloat16*)pWKl, nW4);
    proj_kernel<<<pgrid, 256, PJ_SMEM, s2>>>((const __nv_bfloat16*)pKAh, (const __nv_bfloat16*)pKAl,
        (const __nv_bfloat16*)pWKh, (const __nv_bfloat16*)pWKl,
        (float*)0, (__half*)pKf, 0, 1.0f);
    cudaEventRecord(evK, s2);

    cudaStreamWaitEvent(s3, evA, 0);
    conv_split_kernel<<<nA4 / 256, 256, 0, s3>>>((const float4*)value,
        (__nv_bfloat16*)pVAh, (__nv_bfloat16*)pVAl, nA4);
    conv_split_kernel<<<nW4 / 256, 256, 0, s3>>>((const float4*)Wv,
        (__nv_bfloat16*)pWVh, (__nv_bfloat16*)pWVl, nW4);
    proj_kernel<<<pgrid, 256, PJ_SMEM, s3>>>((const __nv_bfloat16*)pVAh, (const __nv_bfloat16*)pVAl,
        (const __nv_bfloat16*)pWVh, (const __nv_bfloat16*)pWVl,
        (float*)0, (__half*)pVt, 1, 1.0f);
    cudaEventRecord(evV, s3);

    conv_split_kernel<<<nA4 / 256, 256>>>((const float4*)query,
        (__nv_bfloat16*)pQAh, (__nv_bfloat16*)pQAl, nA4);
    conv_split_kernel<<<nW4 / 256, 256>>>((const float4*)Wq,
        (__nv_bfloat16*)pWQh, (__nv_bfloat16*)pWQl, nW4);
    proj_kernel<<<pgrid, 256, PJ_SMEM>>>((const __nv_bfloat16*)pQAh, (const __nv_bfloat16*)pQAl,
        (const __nv_bfloat16*)pWQh, (const __nv_bfloat16*)pWQl,
        (float*)0, (__half*)pQf, 0, SCL);

    cudaStreamWaitEvent(0, evB, 0);
    cudaStreamWaitEvent(0, evK, 0);
    cudaStreamWaitEvent(0, evV, 0);
    attn_kernel<<<dim3(NB * NH, NL / 128), 256, AT_SMEM>>>(att);

    proj_kernel<<<pgrid, 256, PJ_SMEM>>>((const __nv_bfloat16*)pCh, (const __nv_bfloat16*)pCl,
        (const __nv_bfloat16*)pWOh, (const __nv_bfloat16*)pWOl,
        (float*)pPf, (__half*)0, 2, 1.0f);
    ln_kernel<<<TOK, 256>>>((const float*)pPf, query, out);

    cudaEventDestroy(evA); cudaEventDestroy(evB);
    cudaEventDestroy(evK); cudaEventDestroy(evV);
    cudaStreamDestroy(s1); cudaStreamDestroy(s2); cudaStreamDestroy(s3);
}

// round 17
// speedup vs baseline: 1.0993x; 1.0335x over previous
#include <cuda_runtime.h>
#include <cuda_bf16.h>
#include <cuda_fp16.h>
#include <math.h>
#include <stdint.h>

#define NB 8
#define NL 1024
#define ND 512
#define NH 8
#define NDH 64
#define TOK (NB * NL)
#define ACT_ELEMS ((size_t)TOK * ND)
#define W_ELEMS ((size_t)ND * ND)
#define ATT_ELEMS ((size_t)NB * NH * NL * NL)
#define MASK_WORDS (ATT_ELEMS / 32)

typedef unsigned long long ull;

__device__ __nv_bfloat16 g_QAh[ACT_ELEMS], g_QAl[ACT_ELEMS];
__device__ __nv_bfloat16 g_KAh[ACT_ELEMS], g_KAl[ACT_ELEMS];
__device__ __nv_bfloat16 g_VAh[ACT_ELEMS], g_VAl[ACT_ELEMS];
__device__ __nv_bfloat16 g_WQh[W_ELEMS], g_WQl[W_ELEMS];
__device__ __nv_bfloat16 g_WKh[W_ELEMS], g_WKl[W_ELEMS];
__device__ __nv_bfloat16 g_WVh[W_ELEMS], g_WVl[W_ELEMS];
__device__ __nv_bfloat16 g_WOh[W_ELEMS], g_WOl[W_ELEMS];
__device__ __half       g_Qf[ACT_ELEMS], g_Kf[ACT_ELEMS];   // Q pre-scaled f16
__device__ __half       g_Vt[ACT_ELEMS];                    // [bh*64+d][1024] f16
__device__ __nv_bfloat16 g_Ch[ACT_ELEMS], g_Cl[ACT_ELEMS];
__device__ float        g_projf[ACT_ELEMS];
__device__ unsigned     g_am[MASK_WORDS], g_sm[MASK_WORDS];
__device__ int          g_mask_mode;

// ---------------- helpers ----------------
__device__ __forceinline__ uint32_t smem_u32(const void* p) {
    uint32_t a;
    asm("{ .reg .u64 t; cvta.to.shared.u64 t, %1; cvt.u32.u64 %0, t; }" : "=r"(a) : "l"(p));
    return a;
}
__device__ __forceinline__ void ldm_x4(unsigned r[4], uint32_t a) {
    asm volatile("ldmatrix.sync.aligned.m8n8.x4.shared.b16 {%0,%1,%2,%3}, [%4];"
                 : "=r"(r[0]), "=r"(r[1]), "=r"(r[2]), "=r"(r[3]) : "r"(a) : "memory");
}
#define MMA(c, a, b) \
    asm volatile("mma.sync.aligned.m16n8k16.row.col.f32.bf16.bf16.f32 " \
                 "{%0,%1,%2,%3},{%4,%5,%6,%7},{%8,%9},{%0,%1,%2,%3};" \
                 : "+f"((c)[0]), "+f"((c)[1]), "+f"((c)[2]), "+f"((c)[3]) \
                 : "r"((a)[0]), "r"((a)[1]), "r"((a)[2]), "r"((a)[3]), \
                   "r"((b)[0]), "r"((b)[1]))
#define MMAH(c, a, b) \
    asm volatile("mma.sync.aligned.m16n8k16.row.col.f32.f16.f16.f32 " \
                 "{%0,%1,%2,%3},{%4,%5,%6,%7},{%8,%9},{%0,%1,%2,%3};" \
                 : "+f"((c)[0]), "+f"((c)[1]), "+f"((c)[2]), "+f"((c)[3]) \
                 : "r"((a)[0]), "r"((a)[1]), "r"((a)[2]), "r"((a)[3]), \
                   "r"((b)[0]), "r"((b)[1]))

#define CP16(dst, src) \
    asm volatile("cp.async.cg.shared.global [%0], [%1], 16;" :: "r"(dst), "l"(src) : "memory")
#define CP_COMMIT() asm volatile("cp.async.commit_group;" ::: "memory")
#define CP_WAIT(n)  asm volatile("cp.async.wait_group %0;" :: "n"(n) : "memory")

__device__ __forceinline__ ull pack2(float lo, float hi) {
    ull r; asm("mov.b64 %0,{%1,%2};" : "=l"(r) : "f"(lo), "f"(hi)); return r;
}
__device__ __forceinline__ void unpack2(ull v, float& lo, float& hi) {
    asm("mov.b64 {%0,%1},%2;" : "=f"(lo), "=f"(hi) : "l"(v));
}
__device__ __forceinline__ ull ffma2(ull a, ull b, ull c) {
    ull d; asm("fma.rn.f32x2 %0,%1,%2,%3;" : "=l"(d) : "l"(a), "l"(b), "l"(c));
    return d;
}
__device__ __forceinline__ ull add2(ull a, ull b) {
    ull d; asm("add.rn.f32x2 %0,%1,%2;" : "=l"(d) : "l"(a), "l"(b));
    return d;
}
__device__ __forceinline__ ull sub2(ull a, ull b) {
    ull d; asm("sub.rn.f32x2 %0,%1,%2;" : "=l"(d) : "l"(a), "l"(b));
    return d;
}

__device__ __forceinline__ void split2(float f0, float f1, unsigned& hp, unsigned& lp) {
    __nv_bfloat16 h0 = __float2bfloat16_rn(f0), h1 = __float2bfloat16_rn(f1);
    __nv_bfloat16 l0 = __float2bfloat16_rn(f0 - __bfloat162float(h0));
    __nv_bfloat16 l1 = __float2bfloat16_rn(f1 - __bfloat162float(h1));
    hp = (unsigned)__bfloat16_as_ushort(h0) | ((unsigned)__bfloat16_as_ushort(h1) << 16);
    lp = (unsigned)__bfloat16_as_ushort(l0) | ((unsigned)__bfloat16_as_ushort(l1) << 16);
}
__device__ __forceinline__ unsigned packh2(float f0, float f1) {
    __half2 h = __floats2half2_rn(f0, f1);
    return *(unsigned*)&h;
}

// packed exp2 pair, no clamp (caller guarantees -126 < t < 30)
#define EC4 0x3C5E1D6F3C5E1D6Full
#define EC3 0x3D551C733D551C73ull
#define EC2 0x3E7724DF3E7724DFull
#define EC1 0x3F315F4B3F315F4Bull
#define EC0 0x3F8000203F800020ull
__device__ __forceinline__ void fexp2x2(float t0, float t1, float& r0, float& r1) {
    int i0 = __float2int_rd(t0), i1 = __float2int_rd(t1);
    ull f = sub2(pack2(t0, t1), pack2(__int2float_rn(i0), __int2float_rn(i1)));
    ull p = ffma2(EC4, f, EC3);
    p = ffma2(p, f, EC2);
    p = ffma2(p, f, EC1);
    p = ffma2(p, f, EC0);
    float p0, p1;
    unpack2(p, p0, p1);
    r0 = __int_as_float(__float_as_int(p0) + (i0 << 23));
    r1 = __int_as_float(__float_as_int(p1) + (i1 << 23));
}

// ---------------- prep kernels ----------------
__global__ void detect_mask_kernel(const unsigned* __restrict__ m) {
    __shared__ int f32flag, u8flag;
    if (threadIdx.x == 0) { f32flag = 0; u8flag = 0; }
    __syncthreads();
    int lf = 0, lu = 0;
    for (int i = threadIdx.x; i < 4096; i += blockDim.x) {
        unsigned w = m[i];
        if (w == 0x3f800000u) lf = 1;
        else if (w > 1u) lu = 1;
    }
    if (lf) atomicOr(&f32flag, 1);
    if (lu) atomicOr(&u8flag, 1);
    __syncthreads();
    if (threadIdx.x == 0) g_mask_mode = f32flag ? 2 : (u8flag ? 0 : 1);
}

__global__ void pack_mask_kernel(const void* __restrict__ m, unsigned* __restrict__ out) {
    int w = blockIdx.x * 256 + threadIdx.x;
    if (w >= (int)MASK_WORDS) return;
    int mode = g_mask_mode;
    unsigned bits = 0;
    if (mode == 0) {
        const unsigned* p = (const unsigned*)m + (size_t)w * 8;
#pragma unroll
        for (int j = 0; j < 8; j++) {
            unsigned v = __vcmpne4(p[j], 0u);
            bits |= ((((v & 0x01010101u) * 0x01020408u) >> 24) & 0xFu) << (j * 4);
        }
    } else if (mode == 1) {
        const int* p = (const int*)m + (size_t)w * 32;
#pragma unroll
        for (int j = 0; j < 32; j++) bits |= (unsigned)(p[j] != 0) << j;
    } else {
        const float* p = (const float*)m + (size_t)w * 32;
#pragma unroll
        for (int j = 0; j < 32; j++) bits |= (unsigned)(p[j] != 0.0f) << j;
    }
    out[w] = bits;
}

__global__ void conv_split_kernel(const float4* __restrict__ x,
                                  __nv_bfloat16* __restrict__ hi,
                                  __nv_bfloat16* __restrict__ lo, int n4) {
    int i = blockIdx.x * 256 + threadIdx.x;
    if (i >= n4) return;
    float4 v = x[i];
    unsigned h0, l0, h1, l1;
    split2(v.x, v.y, h0, l0);
    split2(v.z, v.w, h1, l1);
    ((uint2*)hi)[i] = make_uint2(h0, h1);
    ((uint2*)lo)[i] = make_uint2(l0, l1);
}

// ---------------- projection GEMM (mma.sync, 3-term split bf16) ------------
#define SPD 72
#define PJ_AH 0
#define PJ_AL 18432
#define PJ_BH 36864
#define PJ_BL 55296
#define PJ_SMEM 73728

__global__ void __launch_bounds__(256) proj_kernel(
    const __nv_bfloat16* __restrict__ Ah, const __nv_bfloat16* __restrict__ Al,
    const __nv_bfloat16* __restrict__ Bh, const __nv_bfloat16* __restrict__ Bl,
    float* __restrict__ Cf, __half* __restrict__ Oh, int mode, float oscale)
{
    extern __shared__ char smem[];
    const uint32_t sb = smem_u32(smem);
    const int tid = threadIdx.x, w = tid >> 5, lane = tid & 31;
    const int gid = lane >> 2, tig = lane & 3;
    const int m0 = blockIdx.x * 128, n0 = blockIdx.y * 128;
    const int wm = (w >> 2) * 64, wn = (w & 3) * 32;
    const int rowsel = (lane & 7) + ((lane >> 4) << 3);
    const int colsel = ((lane >> 3) & 1) * 8;

    float c[4][4][4];
#pragma unroll
    for (int mt = 0; mt < 4; mt++)
#pragma unroll
        for (int nt = 0; nt < 4; nt++)
#pragma unroll
            for (int j = 0; j < 4; j++) c[mt][nt][j] = 0.0f;

    const uint32_t aAddr = sb + ((unsigned)(wm + (lane & 15)) * SPD + (lane >> 4) * 8) * 2;
    const uint32_t bAddr4 = sb + ((unsigned)(wn + rowsel) * SPD + colsel) * 2;

    for (int kc = 0; kc < 512; kc += 64) {
#pragma unroll
        for (int it = 0; it < 4; it++) {
            int idx = it * 256 + tid, row = idx >> 3, cu = idx & 7;
            *(uint4*)(smem + PJ_AH + row * 144 + cu * 16) =
                *(const uint4*)(Ah + (size_t)(m0 + row) * 512 + kc + cu * 8);
            *(uint4*)(smem + PJ_AL + row * 144 + cu * 16) =
                *(const uint4*)(Al + (size_t)(m0 + row) * 512 + kc + cu * 8);
            *(uint4*)(smem + PJ_BH + row * 144 + cu * 16) =
                *(const uint4*)(Bh + (size_t)(n0 + row) * 512 + kc + cu * 8);
            *(uint4*)(smem + PJ_BL + row * 144 + cu * 16) =
                *(const uint4*)(Bl + (size_t)(n0 + row) * 512 + kc + cu * 8);
        }
        __syncthreads();
#pragma unroll
        for (int ks = 0; ks < 4; ks++) {
            unsigned ah[4][4], al[4][4], bh4[2][4], bl4[2][4];
#pragma unroll
            for (int mt = 0; mt < 4; mt++) {
                ldm_x4(ah[mt], aAddr + PJ_AH + (mt * 16 * SPD + ks * 16) * 2);
                ldm_x4(al[mt], aAddr + PJ_AL + (mt * 16 * SPD + ks * 16) * 2);
            }
#pragma unroll
            for (int p = 0; p < 2; p++) {
                ldm_x4(bh4[p], bAddr4 + PJ_BH + (p * 16 * SPD + ks * 16) * 2);
                ldm_x4(bl4[p], bAddr4 + PJ_BL + (p * 16 * SPD + ks * 16) * 2);
            }
#pragma unroll
            for (int mt = 0; mt < 4; mt++)
#pragma unroll
                for (int nt = 0; nt < 4; nt++) {
                    unsigned* bh = &bh4[nt >> 1][(nt & 1) * 2];
                    unsigned* bl = &bl4[nt >> 1][(nt & 1) * 2];
                    MMA(c[mt][nt], ah[mt], bh);
                    MMA(c[mt][nt], ah[mt], bl);
                    MMA(c[mt][nt], al[mt], bh);
                }
        }
        __syncthreads();
    }

    if (mode == 1) {
        float* stage = (float*)smem;  // 128 x 129 f32
#pragma unroll
        for (int mt = 0; mt < 4; mt++)
#pragma unroll
            for (int nt = 0; nt < 4; nt++) {
                int r0 = wm + mt * 16 + gid, cc0 = wn + nt * 8 + 2 * tig;
                stage[r0 * 129 + cc0] = c[mt][nt][0];
                stage[r0 * 129 + cc0 + 1] = c[mt][nt][1];
                stage[(r0 + 8) * 129 + cc0] = c[mt][nt][2];
                stage[(r0 + 8) * 129 + cc0 + 1] = c[mt][nt][3];
            }
        __syncthreads();
        const int bb = m0 >> 10, seq0 = m0 & 1023;
        const int m_local = tid & 127, nsel = tid >> 7;
#pragma unroll 8
        for (int rep = 0; rep < 64; rep++) {
            int n_local = rep * 2 + nsel;
            int n = n0 + n_local;
            int hh = n >> 6, dh = n & 63;
            size_t ob = ((size_t)((bb * 8 + hh) * 64 + dh)) * 1024 + seq0 + m_local;
            Oh[ob] = __float2half_rn(stage[m_local * 129 + n_local]);
        }
    } else if (mode == 2) {
#pragma unroll
        for (int mt = 0; mt < 4; mt++)
#pragma unroll
            for (int nt = 0; nt < 4; nt++) {
                int r0 = m0 + wm + mt * 16 + gid, cc0 = n0 + wn + nt * 8 + 2 * tig;
                *(float2*)(Cf + (size_t)r0 * 512 + cc0) =
                    make_float2(c[mt][nt][0], c[mt][nt][1]);
                *(float2*)(Cf + (size_t)(r0 + 8) * 512 + cc0) =
                    make_float2(c[mt][nt][2], c[mt][nt][3]);
            }
    } else {
#pragma unroll
        for (int mt = 0; mt < 4; mt++)
#pragma unroll
            for (int nt = 0; nt < 4; nt++) {
                int r0 = m0 + wm + mt * 16 + gid, cc0 = n0 + wn + nt * 8 + 2 * tig;
                __half2 p0 = __floats2half2_rn(c[mt][nt][0] * oscale, c[mt][nt][1] * oscale);
                __half2 p1 = __floats2half2_rn(c[mt][nt][2] * oscale, c[mt][nt][3] * oscale);
                *(__half2*)(Oh + (size_t)r0 * 512 + cc0) = p0;
                *(__half2*)(Oh + (size_t)(r0 + 8) * 512 + cc0) = p1;
            }
    }
}

// ---------------- two-pass attention: att written ONCE, normalized --------
// pass 1: K-only stream, exp row-sums. pass 2: recompute, p*=inv, store att
// once, PV with normalized P.
// smem: sums 1024 | Q f16 18432 | 2 x (K 9216 + V 9216)
#define AT_Q 1024
#define AT_BUF0 19456
#define AT_BUFSZ 18432
#define K_OFF 0
#define V_OFF 9216
#define AT_SMEM 56320

__global__ void __launch_bounds__(256, 2) attn_kernel(float* __restrict__ att)
{
    extern __shared__ char smem[];
    const uint32_t sb = smem_u32(smem);
    float* sums = (float*)smem;
    const int tid = threadIdx.x, w = tid >> 5, lane = tid & 31;
    const int gid = lane >> 2, tig = lane & 3;
    const int bh = blockIdx.x, b = bh >> 3, h = bh & 7;
    const int q0 = blockIdx.y * 128;
    const int rowsel = (lane & 7) + ((lane >> 4) << 3);
    const int colsel = ((lane >> 3) & 1) * 8;
    const unsigned klane = ((unsigned)rowsel * SPD + colsel) * 2;

    {
        const size_t qoff = ((size_t)(b * 1024 + q0)) * 512 + h * 64;
#pragma unroll
        for (int it = 0; it < 4; it++) {
            int idx = it * 256 + tid, row = idx >> 3, cu = idx & 7;
            *(uint4*)(smem + AT_Q + row * 144 + cu * 16) =
                *(const uint4*)(g_Qf + qoff + (size_t)row * 512 + cu * 8);
        }
    }
    __syncthreads();
    unsigned aq[4][4];
    {
        const uint32_t qa = sb + AT_Q + ((unsigned)(w * 16 + (lane & 15)) * SPD + (lane >> 4) * 8) * 2;
#pragma unroll
        for (int ks = 0; ks < 4; ks++) ldm_x4(aq[ks], qa + ks * 32);
    }
    __syncthreads();

    const size_t rb0 = (size_t)(b * 1024 + q0 + w * 16 + gid) * 32;
    const size_t rb1 = rb0 + 8 * 32;
    const size_t vbase = (size_t)(bh * 64) * 1024;
    const size_t kbase = (size_t)(b * 1024) * 512 + h * 64;

    // ================= PASS 1: exp row-sums (K only) =================
    ull rsp0 = 0ull, rsp1 = 0ull;
    {
        const uint32_t kb0 = sb + AT_BUF0;
#pragma unroll
        for (int it = 0; it < 1; it++) {
            int idx = it * 256 + tid;
            if (idx < 576) {
                int row = idx >> 3, cu = idx & 7;
                CP16(kb0 + K_OFF + row * 144 + cu * 16,
                     g_Kf + kbase + (size_t)row * 512 + cu * 8);
            }
        }
        // 64 rows x 8 chunks of 16B = 512 cp; do with full 256 threads x2
#pragma unroll
        for (int it = 0; it < 2; it++) {
            int idx = it * 256 + tid, row = idx >> 3, cu = idx & 7;
            CP16(kb0 + K_OFF + row * 144 + cu * 16,
                 g_Kf + kbase + (size_t)row * 512 + cu * 8);
        }
        CP_COMMIT();
    }
    for (int c = 0; c < 16; c++) {
        const int kc = c * 64;
        if (c < 15) {
            const uint32_t kb = sb + AT_BUF0 + ((c + 1) & 1) * AT_BUFSZ;
            const size_t koff = kbase + (size_t)(kc + 64) * 512;
#pragma unroll
            for (int it = 0; it < 2; it++) {
                int idx = it * 256 + tid, row = idx >> 3, cu = idx & 7;
                CP16(kb + K_OFF + row * 144 + cu * 16, g_Kf + koff + (size_t)row * 512 + cu * 8);
            }
            CP_COMMIT();
            CP_WAIT(1);
        } else {
            CP_WAIT(0);
        }
        __syncthreads();
        const uint32_t bb = sb + AT_BUF0 + (c & 1) * AT_BUFSZ;
        unsigned aw0[2], aw1[2];
#pragma unroll
        for (int j = 0; j < 2; j++) {
            aw0[j] = g_am[rb0 + (kc >> 5) + j];
            aw1[j] = g_am[rb1 + (kc >> 5) + j];
        }
#pragma unroll
        for (int nt2 = 0; nt2 < 4; nt2++) {
            float cc[2][4];
#pragma unroll
            for (int hh2 = 0; hh2 < 2; hh2++)
#pragma unroll
                for (int j = 0; j < 4; j++) cc[hh2][j] = 0.0f;
#pragma unroll
            for (int ks = 0; ks < 4; ks++) {
                unsigned kh4[4];
                ldm_x4(kh4, bb + K_OFF + klane + (nt2 * 16 * SPD + ks * 16) * 2);
                MMAH(cc[0], aq[ks], &kh4[0]);
                MMAH(cc[1], aq[ks], &kh4[2]);
            }
#pragma unroll
            for (int half = 0; half < 2; half++) {
                int bidx = (nt2 * 2 + half) * 8 + 2 * tig;
                unsigned w0 = aw0[bidx >> 5], w1 = aw1[bidx >> 5];
                int bo = bidx & 31;
                float t0 = cc[half][0], t1 = cc[half][1];
                float t2 = cc[half][2], t3 = cc[half][3];
                if ((w0 >> bo) & 1u) t0 = -100.0f;
                if ((w0 >> (bo + 1)) & 1u) t1 = -100.0f;
                if ((w1 >> bo) & 1u) t2 = -100.0f;
                if ((w1 >> (bo + 1)) & 1u) t3 = -100.0f;
                float p0, p1, p2, p3;
                fexp2x2(t0, t1, p0, p1);
                fexp2x2(t2, t3, p2, p3);
                rsp0 = add2(rsp0, pack2(p0, p1));
                rsp1 = add2(rsp1, pack2(p2, p3));
            }
        }
        __syncthreads();
    }

    float rs0a, rs0b, rs1a, rs1b;
    unpack2(rsp0, rs0a, rs0b);
    unpack2(rsp1, rs1a, rs1b);
    float rs0 = rs0a + rs0b, rs1 = rs1a + rs1b;
    rs0 += __shfl_xor_sync(0xffffffffu, rs0, 1);
    rs0 += __shfl_xor_sync(0xffffffffu, rs0, 2);
    rs1 += __shfl_xor_sync(0xffffffffu, rs1, 1);
    rs1 += __shfl_xor_sync(0xffffffffu, rs1, 2);
    if (tig == 0) {
        sums[w * 16 + gid] = rs0;
        sums[w * 16 + gid + 8] = rs1;
    }
    __syncthreads();
    if (tid < 128) sums[tid] = 1.0f / sums[tid];
    __syncthreads();
    const float inv0 = sums[w * 16 + gid];
    const float inv1 = sums[w * 16 + gid + 8];
    __syncthreads();

    // ================= PASS 2: recompute + write once + PV ===========
    float ctx[8][4];
#pragma unroll
    for (int dt = 0; dt < 8; dt++)
#pragma unroll
        for (int j = 0; j < 4; j++) ctx[dt][j] = 0.0f;

    float* arow0 = att ? att + ((size_t)(bh * 1024 + q0 + w * 16 + gid)) * 1024 : (float*)0;
    float* arow1 = arow0 ? arow0 + (size_t)8 * 1024 : (float*)0;

    {
        const uint32_t kb = sb + AT_BUF0;
#pragma unroll
        for (int it = 0; it < 2; it++) {
            int idx = it * 256 + tid, row = idx >> 3, cu = idx & 7;
            CP16(kb + K_OFF + row * 144 + cu * 16, g_Kf + kbase + (size_t)row * 512 + cu * 8);
            CP16(kb + V_OFF + row * 144 + cu * 16, g_Vt + vbase + (size_t)row * 1024 + cu * 8);
        }
        CP_COMMIT();
    }
    for (int c = 0; c < 16; c++) {
        const int kc = c * 64;
        if (c < 15) {
            const uint32_t kb = sb + AT_BUF0 + ((c + 1) & 1) * AT_BUFSZ;
            const size_t koff = kbase + (size_t)(kc + 64) * 512;
#pragma unroll
            for (int it = 0; it < 2; it++) {
                int idx = it * 256 + tid, row = idx >> 3, cu = idx & 7;
                CP16(kb + K_OFF + row * 144 + cu * 16, g_Kf + koff + (size_t)row * 512 + cu * 8);
                CP16(kb + V_OFF + row * 144 + cu * 16,
                     g_Vt + vbase + (size_t)row * 1024 + kc + 64 + cu * 8);
            }
            CP_COMMIT();
            CP_WAIT(1);
        } else {
            CP_WAIT(0);
        }
        __syncthreads();

        const uint32_t bb = sb + AT_BUF0 + (c & 1) * AT_BUFSZ;
        unsigned aw0[2], aw1[2], sw0[2], sw1[2];
#pragma unroll
        for (int j = 0; j < 2; j++) {
            aw0[j] = g_am[rb0 + (kc >> 5) + j];
            aw1[j] = g_am[rb1 + (kc >> 5) + j];
            sw0[j] = g_sm[rb0 + (kc >> 5) + j];
            sw1[j] = g_sm[rb1 + (kc >> 5) + j];
        }
#pragma unroll
        for (int nt2 = 0; nt2 < 4; nt2++) {
            float cc[2][4];
#pragma unroll
            for (int hh2 = 0; hh2 < 2; hh2++)
#pragma unroll
                for (int j = 0; j < 4; j++) cc[hh2][j] = 0.0f;
#pragma unroll
            for (int ks = 0; ks < 4; ks++) {
                unsigned kh4[4];
                ldm_x4(kh4, bb + K_OFF + klane + (nt2 * 16 * SPD + ks * 16) * 2);
                MMAH(cc[0], aq[ks], &kh4[0]);
                MMAH(cc[1], aq[ks], &kh4[2]);
            }
            unsigned ph[4];
#pragma unroll
            for (int half = 0; half < 2; half++) {
                int bidx = (nt2 * 2 + half) * 8 + 2 * tig;
                unsigned w0 = aw0[bidx >> 5], w1 = aw1[bidx >> 5];
                unsigned s0 = sw0[bidx >> 5], s1 = sw1[bidx >> 5];
                int bo = bidx & 31;
                float t0 = cc[half][0], t1 = cc[half][1];
                float t2 = cc[half][2], t3 = cc[half][3];
                if ((w0 >> bo) & 1u) t0 = -100.0f;
                if ((w0 >> (bo + 1)) & 1u) t1 = -100.0f;
                if ((w1 >> bo) & 1u) t2 = -100.0f;
                if ((w1 >> (bo + 1)) & 1u) t3 = -100.0f;
                float p0, p1, p2, p3;
                fexp2x2(t0, t1, p0, p1);
                fexp2x2(t2, t3, p2, p3);
                p0 *= inv0; p1 *= inv0; p2 *= inv1; p3 *= inv1;
                if ((s0 >> bo) & 1u) p0 = 0.0f;
                if ((s0 >> (bo + 1)) & 1u) p1 = 0.0f;
                if ((s1 >> bo) & 1u) p2 = 0.0f;
                if ((s1 >> (bo + 1)) & 1u) p3 = 0.0f;
                if (arow0) {
                    *(float2*)(arow0 + kc + bidx) = make_float2(p0, p1);
                    *(float2*)(arow1 + kc + bidx) = make_float2(p2, p3);
                }
                ph[half * 2] = packh2(p0, p1);
                ph[half * 2 + 1] = packh2(p2, p3);
            }
#pragma unroll
            for (int dt2 = 0; dt2 < 4; dt2++) {
                unsigned bv[4];
                ldm_x4(bv, bb + V_OFF + klane + (dt2 * 16 * SPD + nt2 * 16) * 2);
                MMAH(ctx[dt2 * 2], ph, &bv[0]);
                MMAH(ctx[dt2 * 2 + 1], ph, &bv[2]);
            }
        }
        __syncthreads();
    }

    // ctx epilogue (already normalized)
    {
        size_t r0 = (size_t)(b * 1024 + q0 + w * 16 + gid) * 512 + h * 64;
        size_t r1 = r0 + (size_t)8 * 512;
#pragma unroll
        for (int dt = 0; dt < 8; dt++) {
            int cc0 = dt * 8 + 2 * tig;
            unsigned hp, lp;
            split2(ctx[dt][0], ctx[dt][1], hp, lp);
            *(unsigned*)(g_Ch + r0 + cc0) = hp;
            *(unsigned*)(g_Cl + r0 + cc0) = lp;
            split2(ctx[dt][2], ctx[dt][3], hp, lp);
            *(unsigned*)(g_Ch + r1 + cc0) = hp;
            *(unsigned*)(g_Cl + r1 + cc0) = lp;
        }
    }
}

// ---------------- residual + LayerNorm ----------------
__global__ void __launch_bounds__(256) ln_kernel(
    const float* __restrict__ proj, const float* __restrict__ res,
    float* __restrict__ out)
{
    __shared__ float reds[8], redq[8];
    const int row = blockIdx.x, tid = threadIdx.x;
    const float* p = proj + (size_t)row * ND;
    const float* rr = res + (size_t)row * ND;
    float x0 = rr[tid] + p[tid];
    float x1 = rr[tid + 256] + p[tid + 256];
    float s = x0 + x1, q = x0 * x0 + x1 * x1;
#pragma unroll
    for (int o = 16; o > 0; o >>= 1) {
        s += __shfl_xor_sync(0xffffffffu, s, o);
        q += __shfl_xor_sync(0xffffffffu, q, o);
    }
    if ((tid & 31) == 0) { reds[tid >> 5] = s; redq[tid >> 5] = q; }
    __syncthreads();
    float ts = 0, tq = 0;
#pragma unroll
    for (int i = 0; i < 8; i++) { ts += reds[i]; tq += redq[i]; }
    float mean = ts * (1.0f / ND);
    float var = tq * (1.0f / ND) - mean * mean;
    float rsv = rsqrtf(var + 1e-5f);
    out[(size_t)row * ND + tid] = (x0 - mean) * rsv;
    out[(size_t)row * ND + tid + 256] = (x1 - mean) * rsv;
}

// ---------------------------------------------------------------------------
extern "C" void kernel_launch(void* const* d_in, const int* in_sizes, int n_in,
                              void* d_out, int out_size)
{
    const float* query = (const float*)d_in[0];
    const float* key   = (const float*)d_in[1];
    const float* value = (const float*)d_in[2];
    const void*  amask = d_in[3];
    const void*  smask = d_in[4];
    const float* Wq = (const float*)d_in[5];
    const float* Wk = (const float*)d_in[6];
    const float* Wv = (const float*)d_in[7];
    const float* Wo = (const float*)d_in[8];

    float* out = (float*)d_out;
    float* att = ((size_t)out_size >= ACT_ELEMS + ATT_ELEMS) ? out + ACT_ELEMS : (float*)0;

    void *pQAh,*pQAl,*pKAh,*pKAl,*pVAh,*pVAl;
    void *pWQh,*pWQl,*pWKh,*pWKl,*pWVh,*pWVl,*pWOh,*pWOl;
    void *pQf,*pKf,*pVt,*pCh,*pCl,*pPf,*pAm,*pSm;
    cudaGetSymbolAddress(&pQAh, g_QAh); cudaGetSymbolAddress(&pQAl, g_QAl);
    cudaGetSymbolAddress(&pKAh, g_KAh); cudaGetSymbolAddress(&pKAl, g_KAl);
    cudaGetSymbolAddress(&pVAh, g_VAh); cudaGetSymbolAddress(&pVAl, g_VAl);
    cudaGetSymbolAddress(&pWQh, g_WQh); cudaGetSymbolAddress(&pWQl, g_WQl);
    cudaGetSymbolAddress(&pWKh, g_WKh); cudaGetSymbolAddress(&pWKl, g_WKl);
    cudaGetSymbolAddress(&pWVh, g_WVh); cudaGetSymbolAddress(&pWVl, g_WVl);
    cudaGetSymbolAddress(&pWOh, g_WOh); cudaGetSymbolAddress(&pWOl, g_WOl);
    cudaGetSymbolAddress(&pQf, g_Qf);   cudaGetSymbolAddress(&pKf, g_Kf);
    cudaGetSymbolAddress(&pVt, g_Vt);
    cudaGetSymbolAddress(&pCh, g_Ch);   cudaGetSymbolAddress(&pCl, g_Cl);
    cudaGetSymbolAddress(&pPf, g_projf);
    cudaGetSymbolAddress(&pAm, g_am);   cudaGetSymbolAddress(&pSm, g_sm);

    cudaFuncSetAttribute(proj_kernel, cudaFuncAttributeMaxDynamicSharedMemorySize, PJ_SMEM);
    cudaFuncSetAttribute(attn_kernel, cudaFuncAttributeMaxDynamicSharedMemorySize, AT_SMEM);

    cudaStream_t s1, s2, s3;
    cudaEvent_t evA, evB, evK, evV;
    cudaStreamCreateWithFlags(&s1, cudaStreamNonBlocking);
    cudaStreamCreateWithFlags(&s2, cudaStreamNonBlocking);
    cudaStreamCreateWithFlags(&s3, cudaStreamNonBlocking);
    cudaEventCreateWithFlags(&evA, cudaEventDisableTiming);
    cudaEventCreateWithFlags(&evB, cudaEventDisableTiming);
    cudaEventCreateWithFlags(&evK, cudaEventDisableTiming);
    cudaEventCreateWithFlags(&evV, cudaEventDisableTiming);

    const int nA4 = (int)(ACT_ELEMS / 4), nW4 = (int)(W_ELEMS / 4);
    dim3 pgrid(TOK / 128, ND / 128);
    const float SCL = 0.18033688011112042f;

    detect_mask_kernel<<<1, 256>>>((const unsigned*)amask);
    cudaEventRecord(evA, 0);

    cudaStreamWaitEvent(s1, evA, 0);
    pack_mask_kernel<<<MASK_WORDS / 256, 256, 0, s1>>>(amask, (unsigned*)pAm);
    pack_mask_kernel<<<MASK_WORDS / 256, 256, 0, s1>>>(smask, (unsigned*)pSm);
    conv_split_kernel<<<nW4 / 256, 256, 0, s1>>>((const float4*)Wo,
        (__nv_bfloat16*)pWOh, (__nv_bfloat16*)pWOl, nW4);
    cudaEventRecord(evB, s1);

    cudaStreamWaitEvent(s2, evA, 0);
    conv_split_kernel<<<nA4 / 256, 256, 0, s2>>>((const float4*)key,
        (__nv_bfloat16*)pKAh, (__nv_bfloat16*)pKAl, nA4);
    conv_split_kernel<<<nW4 / 256, 256, 0, s2>>>((const float4*)Wk,
        (__nv_bfloat16*)pWKh, (__nv_bfloat16*)pWKl, nW4);
    proj_kernel<<<pgrid, 256, PJ_SMEM, s2>>>((const __nv_bfloat16*)pKAh, (const __nv_bfloat16*)pKAl,
        (const __nv_bfloat16*)pWKh, (const __nv_bfloat16*)pWKl,
        (float*)0, (__half*)pKf, 0, 1.0f);
    cudaEventRecord(evK, s2);

    cudaStreamWaitEvent(s3, evA, 0);
    conv_split_kernel<<<nA4 / 256, 256, 0, s3>>>((const float4*)value,
        (__nv_bfloat16*)pVAh, (__nv_bfloat16*)pVAl, nA4);
    conv_split_kernel<<<nW4 / 256, 256, 0, s3>>>((const float4*)Wv,
        (__nv_bfloat16*)pWVh, (__nv_bfloat16*)pWVl, nW4);
    proj_kernel<<<pgrid, 256, PJ_SMEM, s3>>>((const __nv_bfloat16*)pVAh, (const __nv_bfloat16*)pVAl,
        (const __nv_bfloat16*)pWVh, (const __nv_bfloat16*)pWVl,
        (float*)0, (__half*)pVt, 1, 1.0f);
    cudaEventRecord(evV, s3);

    conv_split_kernel<<<nA4 / 256, 256>>>((const float4*)query,
        (__nv_bfloat16*)pQAh, (__nv_bfloat16*)pQAl, nA4);
    conv_split_kernel<<<nW4 / 256, 256>>>((const float4*)Wq,
        (__nv_bfloat16*)pWQh, (__nv_bfloat16*)pWQl, nW4);
    proj_kernel<<<pgrid, 256, PJ_SMEM>>>((const __nv_bfloat16*)pQAh, (const __nv_bfloat16*)pQAl,
        (const __nv_bfloat16*)pWQh, (const __nv_bfloat16*)pWQl,
        (float*)0, (__half*)pQf, 0, SCL);

    cudaStreamWaitEvent(0, evB, 0);
    cudaStreamWaitEvent(0, evK, 0);
    cudaStreamWaitEvent(0, evV, 0);
    attn_kernel<<<dim3(NB * NH, NL / 128), 256, AT_SMEM>>>(att);

    proj_kernel<<<pgrid, 256, PJ_SMEM>>>((const __nv_bfloat16*)pCh, (const __nv_bfloat16*)pCl,
        (const __nv_bfloat16*)pWOh, (const __nv_bfloat16*)pWOl,
        (float*)pPf, (__half*)0, 2, 1.0f);
    ln_kernel<<<TOK, 256>>>((const float*)pPf, query, out);

    cudaEventDestroy(evA); cudaEventDestroy(evB);
    cudaEventDestroy(evK); cudaEventDestroy(evV);
    cudaStreamDestroy(s1); cudaStreamDestroy(s2); cudaStreamDestroy(s3);
}